// round 2
// baseline (speedup 1.0000x reference)
#include <cuda_runtime.h>
#include <cuda_bf16.h>

// Problem constants (fixed by the reference).
#define NN   50000
#define EE   800000
#define RRL  4
#define DH   128
#define DC   1920          // packed GEMM output columns per node
#define LAY  3
#define DMID 32
#define DOUT 40

// ---------------- scratch (device globals; no allocation allowed) ----------
__device__ float  g_Wcat[LAY * DH * DC];          // packed weights [L][K=128][1920]
__device__ float  g_C[(size_t)NN * DC];           // per-node GEMM outputs (384 MB)
__device__ float  g_hacc[(size_t)NN * DH];        // self-path + aggregated messages
__device__ float  g_h[(size_t)NN * DH];           // post-BN activations (next layer input)
__device__ float  g_inv[NN * RRL];                // 1 / max(count, 1) per (node, relation)
__device__ int    g_cnt[NN * RRL];
__device__ int    g_src[EE];
__device__ int    g_seg[EE];                      // dst*4 + etype
__device__ double g_sum[DH];
__device__ double g_sumsq[DH];
__device__ float  g_scale[DH];
__device__ float  g_shift[DH];
__device__ int    g_is64;

// ---------------- dtype detection -----------------------------------------
// If edge_index is really int64 (non-negative, < 2^31), every odd int32 word
// is 0. If it is int32, odd words are random node ids — essentially never all 0.
__global__ void detect_kernel(const int* __restrict__ ei32) {
    __shared__ int nz;
    if (threadIdx.x == 0) nz = 0;
    __syncthreads();
    for (int i = threadIdx.x; i < 4096; i += blockDim.x) {
        if (ei32[2 * i + 1] != 0) nz = 1;
    }
    __syncthreads();
    if (threadIdx.x == 0) g_is64 = (nz == 0) ? 1 : 0;
}

// ---------------- setup kernels -------------------------------------------
__global__ void zero_cnt_kernel() {
    int i = blockIdx.x * blockDim.x + threadIdx.x;
    if (i < NN * RRL) g_cnt[i] = 0;
}

__global__ void prep_edges_kernel(const int* __restrict__ ei32,
                                  const int* __restrict__ et32, int E) {
    int e = blockIdx.x * blockDim.x + threadIdx.x;
    if (e >= E) return;
    int s, d, t;
    if (g_is64) {
        s = ei32[2 * e];
        d = ei32[2 * (E + e)];
        t = et32[2 * e];
    } else {
        s = ei32[e];
        d = ei32[E + e];
        t = et32[e];
    }
    g_src[e] = s;
    int seg = d * RRL + t;
    g_seg[e] = seg;
    atomicAdd(&g_cnt[seg], 1);
}

__global__ void inv_cnt_kernel() {
    int i = blockIdx.x * blockDim.x + threadIdx.x;
    if (i < NN * RRL) g_inv[i] = 1.0f / fmaxf((float)g_cnt[i], 1.0f);
}

// Pack [Wsk | Wfsk | Wrel(r) | Wfilm(r)] into g_Wcat[l][k][col].
__global__ void pack_weights_kernel(const float* __restrict__ Wsk,
                                    const float* __restrict__ Wfsk,
                                    const float* __restrict__ Wr,
                                    const float* __restrict__ Wf) {
    int idx = blockIdx.x * blockDim.x + threadIdx.x;
    const int total = LAY * DH * DC;
    if (idx >= total) return;
    int col = idx % DC;
    int k   = (idx / DC) % DH;
    int l   = idx / (DC * DH);
    float v;
    if (col < 128) {
        v = Wsk[((size_t)l * DH + k) * DH + col];
    } else if (col < 384) {
        v = Wfsk[((size_t)l * DH + k) * 256 + (col - 128)];
    } else if (col < 896) {
        int cc = col - 384; int r = cc >> 7; int c = cc & 127;
        v = Wr[(((size_t)l * RRL + r) * DH + k) * DH + c];
    } else {
        int cc = col - 896; int r = cc >> 8; int c = cc & 255;
        v = Wf[(((size_t)l * RRL + r) * DH + k) * 256 + c];
    }
    g_Wcat[idx] = v;
}

// ---------------- GEMM: C[M,1920] = A[M,128] @ Wcat[l] --------------------
// 128x128 block tile, BK=8, 256 threads, 8x8 micro-tile.
__global__ __launch_bounds__(256) void gemm128_kernel(const float* __restrict__ Ax,
                                                      int use_internal, int layer, int M) {
    __shared__ float As[8][132];
    __shared__ float Bs[8][128];

    const float* A = use_internal ? g_h : Ax;
    const float* B = g_Wcat + (size_t)layer * DH * DC;

    int tid  = threadIdx.x;
    int bm   = blockIdx.y * 128;
    int bn   = blockIdx.x * 128;
    int trow = (tid >> 4) * 8;
    int tcol = (tid & 15) * 8;

    int a_row  = tid >> 1;          // 0..127
    int a_col4 = (tid & 1) * 4;     // 0 or 4
    int b_row  = tid >> 5;          // 0..7
    int b_col4 = (tid & 31) * 4;

    float acc[8][8];
#pragma unroll
    for (int i = 0; i < 8; i++)
#pragma unroll
        for (int j = 0; j < 8; j++) acc[i][j] = 0.0f;

    for (int k0 = 0; k0 < DH; k0 += 8) {
        float4 av = make_float4(0.f, 0.f, 0.f, 0.f);
        int gr = bm + a_row;
        if (gr < M) av = *(const float4*)(A + (size_t)gr * DH + k0 + a_col4);
        As[a_col4 + 0][a_row] = av.x;
        As[a_col4 + 1][a_row] = av.y;
        As[a_col4 + 2][a_row] = av.z;
        As[a_col4 + 3][a_row] = av.w;

        float4 bv = *(const float4*)(B + (size_t)(k0 + b_row) * DC + bn + b_col4);
        *(float4*)&Bs[b_row][b_col4] = bv;
        __syncthreads();

#pragma unroll
        for (int kk = 0; kk < 8; kk++) {
            float ar[8], br[8];
#pragma unroll
            for (int i = 0; i < 8; i++) ar[i] = As[kk][trow + i];
            float4 b0 = *(const float4*)&Bs[kk][tcol];
            float4 b1 = *(const float4*)&Bs[kk][tcol + 4];
            br[0]=b0.x; br[1]=b0.y; br[2]=b0.z; br[3]=b0.w;
            br[4]=b1.x; br[5]=b1.y; br[6]=b1.z; br[7]=b1.w;
#pragma unroll
            for (int i = 0; i < 8; i++)
#pragma unroll
                for (int j = 0; j < 8; j++) acc[i][j] += ar[i] * br[j];
        }
        __syncthreads();
    }

#pragma unroll
    for (int i = 0; i < 8; i++) {
        int gr = bm + trow + i;
        if (gr >= M) continue;
        float* crow = g_C + (size_t)gr * DC + bn + tcol;
        *(float4*)(crow)     = make_float4(acc[i][0], acc[i][1], acc[i][2], acc[i][3]);
        *(float4*)(crow + 4) = make_float4(acc[i][4], acc[i][5], acc[i][6], acc[i][7]);
    }
}

// ---------------- self path: hacc = relu(gamma_s * skip + beta_s) ---------
__global__ void self_film_kernel(int M) {
    int idx = blockIdx.x * blockDim.x + threadIdx.x;
    if (idx >= M * DH) return;
    int n = idx >> 7;
    int c = idx & 127;
    const float* row = g_C + (size_t)n * DC;
    float skip  = row[c];
    float beta  = row[128 + c];
    float gamma = row[256 + c];
    float v = fmaf(gamma, skip, beta);
    g_hacc[idx] = v > 0.f ? v : 0.f;
}

// ---------------- edge messages: one warp per edge -------------------------
__global__ void edge_msg_kernel(int E) {
    int gtid = blockIdx.x * blockDim.x + threadIdx.x;
    int e    = gtid >> 5;
    int lane = gtid & 31;
    if (e >= E) return;
    int seg = g_seg[e];
    int s   = g_src[e];
    int d   = seg >> 2;
    int t   = seg & 3;
    float invc = g_inv[seg];
    int c0 = lane * 4;

    const float* crow_s = g_C + (size_t)s * DC;
    const float* crow_d = g_C + (size_t)d * DC;
    float4 xr = *(const float4*)(crow_s + 384 + t * 128 + c0);
    float4 be = *(const float4*)(crow_d + 896 + t * 256 + c0);
    float4 ga = *(const float4*)(crow_d + 896 + t * 256 + 128 + c0);

    float m0 = fmaxf(fmaf(ga.x, xr.x, be.x), 0.f) * invc;
    float m1 = fmaxf(fmaf(ga.y, xr.y, be.y), 0.f) * invc;
    float m2 = fmaxf(fmaf(ga.z, xr.z, be.z), 0.f) * invc;
    float m3 = fmaxf(fmaf(ga.w, xr.w, be.w), 0.f) * invc;

    float* hrow = g_hacc + (size_t)d * DH + c0;
    atomicAdd(hrow + 0, m0);
    atomicAdd(hrow + 1, m1);
    atomicAdd(hrow + 2, m2);
    atomicAdd(hrow + 3, m3);
}

// ---------------- batchnorm ------------------------------------------------
__global__ void zero_stats_kernel() {
    int c = threadIdx.x;
    g_sum[c] = 0.0; g_sumsq[c] = 0.0;
}

__global__ void bn_stats_kernel(int M) {
    int c = threadIdx.x;  // 128 threads
    float s = 0.f, s2 = 0.f;
    for (int r = blockIdx.x; r < M; r += gridDim.x) {
        float v = g_hacc[(size_t)r * DH + c];
        s += v;
        s2 += v * v;
    }
    atomicAdd(&g_sum[c], (double)s);
    atomicAdd(&g_sumsq[c], (double)s2);
}

__global__ void bn_final_kernel(const float* __restrict__ bnw,
                                const float* __restrict__ bnb, int M) {
    int c = threadIdx.x;
    double mu  = g_sum[c] / (double)M;
    double var = g_sumsq[c] / (double)M - mu * mu;
    float sc = bnw[c] * rsqrtf((float)var + 1e-5f);
    g_scale[c] = sc;
    g_shift[c] = bnb[c] - (float)mu * sc;
}

__global__ void bn_apply_kernel(int M) {
    int idx = blockIdx.x * blockDim.x + threadIdx.x;
    if (idx >= M * DH) return;
    int c = idx & 127;
    g_h[idx] = fmaf(g_hacc[idx], g_scale[c], g_shift[c]);
}

// ---------------- MLP head (applies last BN inline) ------------------------
__global__ __launch_bounds__(128) void mlp_kernel(const float* __restrict__ w1,
                                                  const float* __restrict__ b1,
                                                  const float* __restrict__ w2,
                                                  const float* __restrict__ b2,
                                                  float* __restrict__ out, int M) {
    __shared__ float s_w1[DH * DMID];
    __shared__ float s_w2[DMID * DOUT];
    __shared__ float s_b1[DMID];
    __shared__ float s_b2[DOUT];
    __shared__ float s_sc[DH], s_sh[DH];
    int tid = threadIdx.x;
    for (int i = tid; i < DH * DMID; i += blockDim.x) s_w1[i] = w1[i];
    for (int i = tid; i < DMID * DOUT; i += blockDim.x) s_w2[i] = w2[i];
    if (tid < DMID) s_b1[tid] = b1[tid];
    if (tid < DOUT) s_b2[tid] = b2[tid];
    if (tid < DH) { s_sc[tid] = g_scale[tid]; s_sh[tid] = g_shift[tid]; }
    __syncthreads();

    int n = blockIdx.x * blockDim.x + tid;
    if (n >= M) return;

    float mid[DMID];
#pragma unroll
    for (int j = 0; j < DMID; j++) mid[j] = s_b1[j];

    const float* hrow = g_hacc + (size_t)n * DH;
    for (int c = 0; c < DH; c++) {
        float hv = fmaf(hrow[c], s_sc[c], s_sh[c]);
#pragma unroll
        for (int j = 0; j < DMID; j++) mid[j] = fmaf(hv, s_w1[c * DMID + j], mid[j]);
    }
#pragma unroll
    for (int j = 0; j < DMID; j++) {
        float v = mid[j];
        mid[j] = v > 0.f ? v : 0.2f * v;
    }
    float* orow = out + (size_t)n * DOUT;
#pragma unroll
    for (int o = 0; o < DOUT; o++) {
        float acc = s_b2[o];
#pragma unroll
        for (int j = 0; j < DMID; j++) acc = fmaf(mid[j], s_w2[j * DOUT + o], acc);
        orow[o] = acc;
    }
}

// ---------------- launch ----------------------------------------------------
extern "C" void kernel_launch(void* const* d_in, const int* in_sizes, int n_in,
                              void* d_out, int out_size) {
    const float* x    = (const float*)d_in[0];
    const int*   ei32 = (const int*)d_in[1];
    const int*   et32 = (const int*)d_in[2];
    const float* Wsk  = (const float*)d_in[3];
    const float* Wfsk = (const float*)d_in[4];
    const float* Wr   = (const float*)d_in[5];
    const float* Wf   = (const float*)d_in[6];
    const float* bnw  = (const float*)d_in[7];
    const float* bnb  = (const float*)d_in[8];
    const float* l1w  = (const float*)d_in[9];
    const float* l1b  = (const float*)d_in[10];
    const float* l2w  = (const float*)d_in[11];
    const float* l2b  = (const float*)d_in[12];
    float* out = (float*)d_out;

    const int E = in_sizes[2];        // 800000 (element count, dtype-agnostic)
    const int M = in_sizes[0] / DH;   // 50000

    // Edge counts / inverse means (layer-invariant) + weight packing.
    detect_kernel<<<1, 256>>>(ei32);
    zero_cnt_kernel<<<(NN * RRL + 255) / 256, 256>>>();
    prep_edges_kernel<<<(E + 255) / 256, 256>>>(ei32, et32, E);
    inv_cnt_kernel<<<(NN * RRL + 255) / 256, 256>>>();
    pack_weights_kernel<<<(LAY * DH * DC + 255) / 256, 256>>>(Wsk, Wfsk, Wr, Wf);

    dim3 gemm_grid(DC / 128, (M + 127) / 128);
    for (int l = 0; l < LAY; l++) {
        gemm128_kernel<<<gemm_grid, 256>>>(x, l == 0 ? 0 : 1, l, M);
        self_film_kernel<<<(M * DH + 255) / 256, 256>>>(M);
        edge_msg_kernel<<<(E * 32 + 255) / 256, 256>>>(E);
        zero_stats_kernel<<<1, 128>>>();
        bn_stats_kernel<<<296, 128>>>(M);
        bn_final_kernel<<<1, 128>>>(bnw + l * DH, bnb + l * DH, M);
        if (l < LAY - 1) bn_apply_kernel<<<(M * DH + 255) / 256, 256>>>(M);
    }
    mlp_kernel<<<(M + 127) / 128, 128>>>(l1w, l1b, l2w, l2b, out, M);
}

// round 3
// speedup vs baseline: 1.1285x; 1.1285x over previous
#include <cuda_runtime.h>
#include <cuda_bf16.h>

// Problem constants (fixed by the reference).
#define NN   50000
#define EE   800000
#define RRL  4
#define DH   128
#define DC   1920
#define LAY  3
#define DMID 32
#define DOUT 40
#define NSEG (NN * RRL)          // 200000
#define SCAN_B 196               // ceil(NSEG / 1024)

// ---------------- scratch (device globals) ---------------------------------
__device__ float  g_Wcat[LAY * DH * DC];
__device__ float  g_C[(size_t)NN * DC];           // packed GEMM outputs (384 MB)
__device__ float  g_hacc[(size_t)NN * DH];
__device__ int    g_cnt[NSEG];
__device__ int    g_off[NSEG];
__device__ int    g_cur[NSEG];
__device__ int    g_src[EE];
__device__ int    g_seg[EE];
__device__ int    g_srcs[EE];                     // srcs sorted by segment
__device__ int    g_bsum[SCAN_B];
__device__ int    g_bsum_ex[SCAN_B];
__device__ double g_sum[DH];
__device__ double g_sumsq[DH];
__device__ float  g_scale[DH];
__device__ float  g_shift[DH];
__device__ int    g_is64;

// ---------------- f32x2 helpers --------------------------------------------
__device__ __forceinline__ unsigned long long pack2(float v) {
    unsigned long long r;
    asm("mov.b64 %0, {%1, %1};" : "=l"(r) : "f"(v));
    return r;
}
__device__ __forceinline__ float2 unpk2(unsigned long long u) {
    float2 f;
    asm("mov.b64 {%0, %1}, %2;" : "=f"(f.x), "=f"(f.y) : "l"(u));
    return f;
}
#define FMA2(d, a, b) asm("fma.rn.f32x2 %0, %1, %2, %0;" : "+l"(d) : "l"(a), "l"(b))

// ---------------- dtype detection ------------------------------------------
__global__ void detect_kernel(const int* __restrict__ ei32) {
    __shared__ int nz;
    if (threadIdx.x == 0) nz = 0;
    __syncthreads();
    for (int i = threadIdx.x; i < 4096; i += blockDim.x)
        if (ei32[2 * i + 1] != 0) nz = 1;
    __syncthreads();
    if (threadIdx.x == 0) g_is64 = (nz == 0) ? 1 : 0;
}

// ---------------- edge prep -------------------------------------------------
__global__ void zero_cnt_kernel() {
    int i = blockIdx.x * blockDim.x + threadIdx.x;
    if (i < NSEG) g_cnt[i] = 0;
}

__global__ void prep_edges_kernel(const int* __restrict__ ei32,
                                  const int* __restrict__ et32, int E) {
    int e = blockIdx.x * blockDim.x + threadIdx.x;
    if (e >= E) return;
    int s, d, t;
    if (g_is64) { s = ei32[2 * e]; d = ei32[2 * (E + e)]; t = et32[2 * e]; }
    else        { s = ei32[e];     d = ei32[E + e];       t = et32[e];     }
    g_src[e] = s;
    int seg = d * RRL + t;
    g_seg[e] = seg;
    atomicAdd(&g_cnt[seg], 1);
}

__global__ void scan1_kernel() {
    __shared__ int sh[1024];
    int tid = threadIdx.x;
    int g = blockIdx.x * 1024 + tid;
    int v = (g < NSEG) ? g_cnt[g] : 0;
    sh[tid] = v;
    __syncthreads();
    for (int o = 1; o < 1024; o <<= 1) {
        int t = 0;
        if (tid >= o) t = sh[tid - o];
        __syncthreads();
        sh[tid] += t;
        __syncthreads();
    }
    if (g < NSEG) g_off[g] = sh[tid] - v;       // exclusive within block
    if (tid == 1023) g_bsum[blockIdx.x] = sh[1023];
}

__global__ void scan2_kernel() {
    __shared__ int sh[256];
    int tid = threadIdx.x;
    int v = (tid < SCAN_B) ? g_bsum[tid] : 0;
    sh[tid] = v;
    __syncthreads();
    for (int o = 1; o < 256; o <<= 1) {
        int t = 0;
        if (tid >= o) t = sh[tid - o];
        __syncthreads();
        sh[tid] += t;
        __syncthreads();
    }
    if (tid < SCAN_B) g_bsum_ex[tid] = sh[tid] - v;
}

__global__ void scan3_kernel() {
    int g = blockIdx.x * blockDim.x + threadIdx.x;
    if (g >= NSEG) return;
    int o = g_off[g] + g_bsum_ex[g >> 10];
    g_off[g] = o;
    g_cur[g] = o;
}

__global__ void scatter_kernel(int E) {
    int e = blockIdx.x * blockDim.x + threadIdx.x;
    if (e >= E) return;
    int pos = atomicAdd(&g_cur[g_seg[e]], 1);
    g_srcs[pos] = g_src[e];
}

// ---------------- weight packing -------------------------------------------
__global__ void pack_weights_kernel(const float* __restrict__ Wsk,
                                    const float* __restrict__ Wfsk,
                                    const float* __restrict__ Wr,
                                    const float* __restrict__ Wf) {
    int idx = blockIdx.x * blockDim.x + threadIdx.x;
    const int total = LAY * DH * DC;
    if (idx >= total) return;
    int col = idx % DC;
    int k   = (idx / DC) % DH;
    int l   = idx / (DC * DH);
    float v;
    if (col < 128) {
        v = Wsk[((size_t)l * DH + k) * DH + col];
    } else if (col < 384) {
        v = Wfsk[((size_t)l * DH + k) * 256 + (col - 128)];
    } else if (col < 896) {
        int cc = col - 384; int r = cc >> 7; int c = cc & 127;
        v = Wr[(((size_t)l * RRL + r) * DH + k) * DH + c];
    } else {
        int cc = col - 896; int r = cc >> 8; int c = cc & 255;
        v = Wf[(((size_t)l * RRL + r) * DH + k) * 256 + c];
    }
    g_Wcat[idx] = v;
}

// ---------------- GEMM: C[M,1920] = bn(A)[M,128] @ Wcat[l] -----------------
// 128x128 tile, BK=16, double-buffered, 256 threads, 8x8 micro in f32x2.
__global__ __launch_bounds__(256, 2) void gemm_f32x2_kernel(
    const float* __restrict__ Aex, int use_internal, int use_bn, int layer, int M)
{
    __shared__ unsigned long long As2[2][16][130];   // A duplicated pairs [k][m]
    __shared__ float Bs[2][16][128];
    __shared__ float s_sc[DH], s_sh[DH];

    const float* A = use_internal ? g_hacc : Aex;
    const float* W = g_Wcat + (size_t)layer * DH * DC;

    int tid = threadIdx.x;
    int bm = blockIdx.y * 128;
    int bn = blockIdx.x * 128;

    int ar_ = tid >> 2;            // 0..63 (rows ar_ and ar_+64)
    int ac_ = (tid & 3) * 4;       // 0,4,8,12 within BK
    int br_ = tid >> 5;            // 0..7  (k rows br_ and br_+8)
    int bc_ = (tid & 31) * 4;

    int trow = (tid >> 4) * 8;
    int tcol = (tid & 15) * 8;

    if (tid < DH) {
        s_sc[tid] = use_bn ? g_scale[tid] : 1.0f;
        s_sh[tid] = use_bn ? g_shift[tid] : 0.0f;
    }
    __syncthreads();

    unsigned long long acc[8][4];
#pragma unroll
    for (int i = 0; i < 8; i++)
#pragma unroll
        for (int j = 0; j < 4; j++) acc[i][j] = 0ull;

    float4 av0, av1, bv0, bv1;

    // ---- load tile 0 into staging regs ----
    {
        int k0 = 0;
        int gr0 = bm + ar_, gr1 = gr0 + 64;
        av0 = (gr0 < M) ? *(const float4*)(A + (size_t)gr0 * DH + k0 + ac_)
                        : make_float4(0.f, 0.f, 0.f, 0.f);
        av1 = (gr1 < M) ? *(const float4*)(A + (size_t)gr1 * DH + k0 + ac_)
                        : make_float4(0.f, 0.f, 0.f, 0.f);
        if (use_bn) {
            int c = k0 + ac_;
            av0.x = fmaf(av0.x, s_sc[c+0], s_sh[c+0]); av1.x = fmaf(av1.x, s_sc[c+0], s_sh[c+0]);
            av0.y = fmaf(av0.y, s_sc[c+1], s_sh[c+1]); av1.y = fmaf(av1.y, s_sc[c+1], s_sh[c+1]);
            av0.z = fmaf(av0.z, s_sc[c+2], s_sh[c+2]); av1.z = fmaf(av1.z, s_sc[c+2], s_sh[c+2]);
            av0.w = fmaf(av0.w, s_sc[c+3], s_sh[c+3]); av1.w = fmaf(av1.w, s_sc[c+3], s_sh[c+3]);
        }
        bv0 = *(const float4*)(W + (size_t)(k0 + br_) * DC + bn + bc_);
        bv1 = *(const float4*)(W + (size_t)(k0 + br_ + 8) * DC + bn + bc_);
    }
    // ---- store tile 0 ----
    {
        As2[0][ac_ + 0][ar_]      = pack2(av0.x);
        As2[0][ac_ + 1][ar_]      = pack2(av0.y);
        As2[0][ac_ + 2][ar_]      = pack2(av0.z);
        As2[0][ac_ + 3][ar_]      = pack2(av0.w);
        As2[0][ac_ + 0][ar_ + 64] = pack2(av1.x);
        As2[0][ac_ + 1][ar_ + 64] = pack2(av1.y);
        As2[0][ac_ + 2][ar_ + 64] = pack2(av1.z);
        As2[0][ac_ + 3][ar_ + 64] = pack2(av1.w);
        *(float4*)&Bs[0][br_][bc_]     = bv0;
        *(float4*)&Bs[0][br_ + 8][bc_] = bv1;
    }
    __syncthreads();

    int p = 0;
#pragma unroll 1
    for (int t = 0; t < 8; t++) {
        if (t < 7) {
            int k0 = (t + 1) * 16;
            int gr0 = bm + ar_, gr1 = gr0 + 64;
            av0 = (gr0 < M) ? *(const float4*)(A + (size_t)gr0 * DH + k0 + ac_)
                            : make_float4(0.f, 0.f, 0.f, 0.f);
            av1 = (gr1 < M) ? *(const float4*)(A + (size_t)gr1 * DH + k0 + ac_)
                            : make_float4(0.f, 0.f, 0.f, 0.f);
            if (use_bn) {
                int c = k0 + ac_;
                av0.x = fmaf(av0.x, s_sc[c+0], s_sh[c+0]); av1.x = fmaf(av1.x, s_sc[c+0], s_sh[c+0]);
                av0.y = fmaf(av0.y, s_sc[c+1], s_sh[c+1]); av1.y = fmaf(av1.y, s_sc[c+1], s_sh[c+1]);
                av0.z = fmaf(av0.z, s_sc[c+2], s_sh[c+2]); av1.z = fmaf(av1.z, s_sc[c+2], s_sh[c+2]);
                av0.w = fmaf(av0.w, s_sc[c+3], s_sh[c+3]); av1.w = fmaf(av1.w, s_sc[c+3], s_sh[c+3]);
            }
            bv0 = *(const float4*)(W + (size_t)(k0 + br_) * DC + bn + bc_);
            bv1 = *(const float4*)(W + (size_t)(k0 + br_ + 8) * DC + bn + bc_);
        }

        // compute on buffer p
#pragma unroll
        for (int kk = 0; kk < 16; kk++) {
            ulonglong2 aa0 = *(const ulonglong2*)&As2[p][kk][trow + 0];
            ulonglong2 aa1 = *(const ulonglong2*)&As2[p][kk][trow + 2];
            ulonglong2 aa2 = *(const ulonglong2*)&As2[p][kk][trow + 4];
            ulonglong2 aa3 = *(const ulonglong2*)&As2[p][kk][trow + 6];
            ulonglong2 bb0 = *(const ulonglong2*)&Bs[p][kk][tcol];
            ulonglong2 bb1 = *(const ulonglong2*)&Bs[p][kk][tcol + 4];
            unsigned long long b0 = bb0.x, b1 = bb0.y, b2 = bb1.x, b3 = bb1.y;
            FMA2(acc[0][0], aa0.x, b0); FMA2(acc[0][1], aa0.x, b1);
            FMA2(acc[0][2], aa0.x, b2); FMA2(acc[0][3], aa0.x, b3);
            FMA2(acc[1][0], aa0.y, b0); FMA2(acc[1][1], aa0.y, b1);
            FMA2(acc[1][2], aa0.y, b2); FMA2(acc[1][3], aa0.y, b3);
            FMA2(acc[2][0], aa1.x, b0); FMA2(acc[2][1], aa1.x, b1);
            FMA2(acc[2][2], aa1.x, b2); FMA2(acc[2][3], aa1.x, b3);
            FMA2(acc[3][0], aa1.y, b0); FMA2(acc[3][1], aa1.y, b1);
            FMA2(acc[3][2], aa1.y, b2); FMA2(acc[3][3], aa1.y, b3);
            FMA2(acc[4][0], aa2.x, b0); FMA2(acc[4][1], aa2.x, b1);
            FMA2(acc[4][2], aa2.x, b2); FMA2(acc[4][3], aa2.x, b3);
            FMA2(acc[5][0], aa2.y, b0); FMA2(acc[5][1], aa2.y, b1);
            FMA2(acc[5][2], aa2.y, b2); FMA2(acc[5][3], aa2.y, b3);
            FMA2(acc[6][0], aa3.x, b0); FMA2(acc[6][1], aa3.x, b1);
            FMA2(acc[6][2], aa3.x, b2); FMA2(acc[6][3], aa3.x, b3);
            FMA2(acc[7][0], aa3.y, b0); FMA2(acc[7][1], aa3.y, b1);
            FMA2(acc[7][2], aa3.y, b2); FMA2(acc[7][3], aa3.y, b3);
        }

        if (t < 7) {
            int q = p ^ 1;
            As2[q][ac_ + 0][ar_]      = pack2(av0.x);
            As2[q][ac_ + 1][ar_]      = pack2(av0.y);
            As2[q][ac_ + 2][ar_]      = pack2(av0.z);
            As2[q][ac_ + 3][ar_]      = pack2(av0.w);
            As2[q][ac_ + 0][ar_ + 64] = pack2(av1.x);
            As2[q][ac_ + 1][ar_ + 64] = pack2(av1.y);
            As2[q][ac_ + 2][ar_ + 64] = pack2(av1.z);
            As2[q][ac_ + 3][ar_ + 64] = pack2(av1.w);
            *(float4*)&Bs[q][br_][bc_]     = bv0;
            *(float4*)&Bs[q][br_ + 8][bc_] = bv1;
            __syncthreads();
            p = q;
        }
    }

#pragma unroll
    for (int i = 0; i < 8; i++) {
        int gr = bm + trow + i;
        if (gr >= M) continue;
        float2 f0 = unpk2(acc[i][0]);
        float2 f1 = unpk2(acc[i][1]);
        float2 f2 = unpk2(acc[i][2]);
        float2 f3 = unpk2(acc[i][3]);
        float* crow = g_C + (size_t)gr * DC + bn + tcol;
        *(float4*)(crow)     = make_float4(f0.x, f0.y, f1.x, f1.y);
        *(float4*)(crow + 4) = make_float4(f2.x, f2.y, f3.x, f3.y);
    }
}

// ---------------- self path -------------------------------------------------
__global__ void self_film_kernel(int M) {
    int idx = blockIdx.x * blockDim.x + threadIdx.x;
    if (idx >= M * DH) return;
    int n = idx >> 7;
    int c = idx & 127;
    const float* row = g_C + (size_t)n * DC;
    float skip  = row[c];
    float beta  = row[128 + c];
    float gamma = row[256 + c];
    float v = fmaf(gamma, skip, beta);
    g_hacc[idx] = v > 0.f ? v : 0.f;
}

// ---------------- segment-sorted edge aggregation ---------------------------
__global__ void seg_msg_kernel() {
    int gt = blockIdx.x * blockDim.x + threadIdx.x;
    int seg = gt >> 5;
    int lane = gt & 31;
    if (seg >= NSEG) return;
    int cnt = g_cnt[seg];
    if (cnt == 0) return;
    int n = seg >> 2;
    int r = seg & 3;
    int c0 = lane * 4;

    const float* dbase = g_C + (size_t)n * DC + 896 + r * 256 + c0;
    float4 be = *(const float4*)(dbase);
    float4 ga = *(const float4*)(dbase + 128);
    float4 acc = make_float4(0.f, 0.f, 0.f, 0.f);
    int base = g_off[seg];
    const float* sb = g_C + 384 + r * 128 + c0;

    for (int i0 = 0; i0 < cnt; i0 += 32) {
        int m = cnt - i0; if (m > 32) m = 32;
        int sv = (lane < m) ? g_srcs[base + i0 + lane] : 0;
        for (int i = 0; i < m; i++) {
            int s = __shfl_sync(0xffffffffu, sv, i);
            float4 xr = *(const float4*)(sb + (size_t)s * DC);
            acc.x += fmaxf(fmaf(ga.x, xr.x, be.x), 0.f);
            acc.y += fmaxf(fmaf(ga.y, xr.y, be.y), 0.f);
            acc.z += fmaxf(fmaf(ga.z, xr.z, be.z), 0.f);
            acc.w += fmaxf(fmaf(ga.w, xr.w, be.w), 0.f);
        }
    }
    float inv = 1.0f / (float)cnt;
    float* h = g_hacc + (size_t)n * DH + c0;
    atomicAdd(h + 0, acc.x * inv);
    atomicAdd(h + 1, acc.y * inv);
    atomicAdd(h + 2, acc.z * inv);
    atomicAdd(h + 3, acc.w * inv);
}

// ---------------- batchnorm stats -------------------------------------------
__global__ void zero_stats_kernel() {
    int c = threadIdx.x;
    g_sum[c] = 0.0; g_sumsq[c] = 0.0;
}

__global__ void bn_stats_kernel(int M) {
    int c = threadIdx.x;  // 128 threads
    float s = 0.f, s2 = 0.f;
    for (int r = blockIdx.x; r < M; r += gridDim.x) {
        float v = g_hacc[(size_t)r * DH + c];
        s += v;
        s2 += v * v;
    }
    atomicAdd(&g_sum[c], (double)s);
    atomicAdd(&g_sumsq[c], (double)s2);
}

__global__ void bn_final_kernel(const float* __restrict__ bnw,
                                const float* __restrict__ bnb, int M) {
    int c = threadIdx.x;
    double mu  = g_sum[c] / (double)M;
    double var = g_sumsq[c] / (double)M - mu * mu;
    float sc = bnw[c] * rsqrtf((float)var + 1e-5f);
    g_scale[c] = sc;
    g_shift[c] = bnb[c] - (float)mu * sc;
}

// ---------------- MLP head (applies last BN inline) ------------------------
__global__ __launch_bounds__(128) void mlp_kernel(const float* __restrict__ w1,
                                                  const float* __restrict__ b1,
                                                  const float* __restrict__ w2,
                                                  const float* __restrict__ b2,
                                                  float* __restrict__ out, int M) {
    __shared__ float s_w1[DH * DMID];
    __shared__ float s_w2[DMID * DOUT];
    __shared__ float s_b1[DMID];
    __shared__ float s_b2[DOUT];
    __shared__ float s_sc[DH], s_sh[DH];
    int tid = threadIdx.x;
    for (int i = tid; i < DH * DMID; i += blockDim.x) s_w1[i] = w1[i];
    for (int i = tid; i < DMID * DOUT; i += blockDim.x) s_w2[i] = w2[i];
    if (tid < DMID) s_b1[tid] = b1[tid];
    if (tid < DOUT) s_b2[tid] = b2[tid];
    if (tid < DH) { s_sc[tid] = g_scale[tid]; s_sh[tid] = g_shift[tid]; }
    __syncthreads();

    int n = blockIdx.x * blockDim.x + tid;
    if (n >= M) return;

    float mid[DMID];
#pragma unroll
    for (int j = 0; j < DMID; j++) mid[j] = s_b1[j];

    const float* hrow = g_hacc + (size_t)n * DH;
    for (int c = 0; c < DH; c++) {
        float hv = fmaf(hrow[c], s_sc[c], s_sh[c]);
#pragma unroll
        for (int j = 0; j < DMID; j++) mid[j] = fmaf(hv, s_w1[c * DMID + j], mid[j]);
    }
#pragma unroll
    for (int j = 0; j < DMID; j++) {
        float v = mid[j];
        mid[j] = v > 0.f ? v : 0.2f * v;
    }
    float* orow = out + (size_t)n * DOUT;
#pragma unroll
    for (int o = 0; o < DOUT; o++) {
        float acc = s_b2[o];
#pragma unroll
        for (int j = 0; j < DMID; j++) acc = fmaf(mid[j], s_w2[j * DOUT + o], acc);
        orow[o] = acc;
    }
}

// ---------------- launch ----------------------------------------------------
extern "C" void kernel_launch(void* const* d_in, const int* in_sizes, int n_in,
                              void* d_out, int out_size) {
    const float* x    = (const float*)d_in[0];
    const int*   ei32 = (const int*)d_in[1];
    const int*   et32 = (const int*)d_in[2];
    const float* Wsk  = (const float*)d_in[3];
    const float* Wfsk = (const float*)d_in[4];
    const float* Wr   = (const float*)d_in[5];
    const float* Wf   = (const float*)d_in[6];
    const float* bnw  = (const float*)d_in[7];
    const float* bnb  = (const float*)d_in[8];
    const float* l1w  = (const float*)d_in[9];
    const float* l1b  = (const float*)d_in[10];
    const float* l2w  = (const float*)d_in[11];
    const float* l2b  = (const float*)d_in[12];
    float* out = (float*)d_out;

    const int E = in_sizes[2];        // 800000
    const int M = in_sizes[0] / DH;   // 50000

    // ---- setup (layer-invariant): edge sort by (dst, rel) + weight packing
    detect_kernel<<<1, 256>>>(ei32);
    zero_cnt_kernel<<<(NSEG + 255) / 256, 256>>>();
    prep_edges_kernel<<<(E + 255) / 256, 256>>>(ei32, et32, E);
    scan1_kernel<<<SCAN_B, 1024>>>();
    scan2_kernel<<<1, 256>>>();
    scan3_kernel<<<(NSEG + 255) / 256, 256>>>();
    scatter_kernel<<<(E + 255) / 256, 256>>>(E);
    pack_weights_kernel<<<(LAY * DH * DC + 255) / 256, 256>>>(Wsk, Wfsk, Wr, Wf);

    dim3 gemm_grid(DC / 128, (M + 127) / 128);
    for (int l = 0; l < LAY; l++) {
        gemm_f32x2_kernel<<<gemm_grid, 256>>>(x, l == 0 ? 0 : 1, l == 0 ? 0 : 1, l, M);
        self_film_kernel<<<(M * DH + 255) / 256, 256>>>(M);
        seg_msg_kernel<<<(NSEG * 32 + 255) / 256, 256>>>();
        zero_stats_kernel<<<1, 128>>>();
        bn_stats_kernel<<<296, 128>>>(M);
        bn_final_kernel<<<1, 128>>>(bnw + l * DH, bnb + l * DH, M);
    }
    mlp_kernel<<<(M + 127) / 128, 128>>>(l1w, l1b, l2w, l2b, out, M);
}

// round 5
// speedup vs baseline: 1.4857x; 1.3166x over previous
#include <cuda_runtime.h>
#include <cuda_bf16.h>
#include <cstdint>

// Problem constants (fixed by the reference).
#define NN   50000
#define EE   800000
#define RRL  4
#define DH   128
#define DC   1920
#define LAY  3
#define DMID 32
#define DOUT 40
#define NSEG (NN * RRL)
#define SCAN_B 196
#define ASTR 136                              // padded SMEM row stride (bf16 elems)
#define GEMM_SMEM (4 * 128 * ASTR * 2)        // A hi/lo + B hi/lo = 139264 B

// ---------------- scratch (device globals) ---------------------------------
__device__ float  g_C[(size_t)NN * DC];
__device__ float  g_hacc[(size_t)NN * DH];
__device__ __nv_bfloat16 g_Ahi[(size_t)NN * DH];
__device__ __nv_bfloat16 g_Alo[(size_t)NN * DH];
__device__ __nv_bfloat16 g_Whi[(size_t)LAY * DC * DH];
__device__ __nv_bfloat16 g_Wlo[(size_t)LAY * DC * DH];
__device__ int    g_cnt[NSEG];
__device__ int    g_off[NSEG];
__device__ int    g_cur[NSEG];
__device__ int    g_src[EE];
__device__ int    g_seg[EE];
__device__ int    g_srcs[EE];
__device__ int    g_bsum[SCAN_B];
__device__ int    g_bsum_ex[SCAN_B];
__device__ double g_sum[DH];
__device__ double g_sumsq[DH];
__device__ float  g_scale[DH];
__device__ float  g_shift[DH];
__device__ int    g_is64;

// ---------------- helpers ----------------------------------------------------
__device__ __forceinline__ uint32_t smem_u32(const void* p) {
    uint32_t a;
    asm("{ .reg .u64 t; cvta.to.shared.u64 t, %1; cvt.u32.u64 %0, t; }" : "=r"(a) : "l"(p));
    return a;
}

// ---------------- dtype detection ------------------------------------------
__global__ void detect_kernel(const int* __restrict__ ei32) {
    __shared__ int nz;
    if (threadIdx.x == 0) nz = 0;
    __syncthreads();
    for (int i = threadIdx.x; i < 4096; i += blockDim.x)
        if (ei32[2 * i + 1] != 0) nz = 1;
    __syncthreads();
    if (threadIdx.x == 0) g_is64 = (nz == 0) ? 1 : 0;
}

// ---------------- edge prep -------------------------------------------------
__global__ void zero_cnt_kernel() {
    int i = blockIdx.x * blockDim.x + threadIdx.x;
    if (i < NSEG) g_cnt[i] = 0;
}

__global__ void prep_edges_kernel(const int* __restrict__ ei32,
                                  const int* __restrict__ et32, int E) {
    int e = blockIdx.x * blockDim.x + threadIdx.x;
    if (e >= E) return;
    int s, d, t;
    if (g_is64) { s = ei32[2 * e]; d = ei32[2 * (E + e)]; t = et32[2 * e]; }
    else        { s = ei32[e];     d = ei32[E + e];       t = et32[e];     }
    g_src[e] = s;
    int seg = d * RRL + t;
    g_seg[e] = seg;
    atomicAdd(&g_cnt[seg], 1);
}

__global__ void scan1_kernel() {
    __shared__ int sh[1024];
    int tid = threadIdx.x;
    int g = blockIdx.x * 1024 + tid;
    int v = (g < NSEG) ? g_cnt[g] : 0;
    sh[tid] = v;
    __syncthreads();
    for (int o = 1; o < 1024; o <<= 1) {
        int t = 0;
        if (tid >= o) t = sh[tid - o];
        __syncthreads();
        sh[tid] += t;
        __syncthreads();
    }
    if (g < NSEG) g_off[g] = sh[tid] - v;
    if (tid == 1023) g_bsum[blockIdx.x] = sh[1023];
}

__global__ void scan2_kernel() {
    __shared__ int sh[256];
    int tid = threadIdx.x;
    int v = (tid < SCAN_B) ? g_bsum[tid] : 0;
    sh[tid] = v;
    __syncthreads();
    for (int o = 1; o < 256; o <<= 1) {
        int t = 0;
        if (tid >= o) t = sh[tid - o];
        __syncthreads();
        sh[tid] += t;
        __syncthreads();
    }
    if (tid < SCAN_B) g_bsum_ex[tid] = sh[tid] - v;
}

__global__ void scan3_kernel() {
    int g = blockIdx.x * blockDim.x + threadIdx.x;
    if (g >= NSEG) return;
    int o = g_off[g] + g_bsum_ex[g >> 10];
    g_off[g] = o;
    g_cur[g] = o;
}

__global__ void scatter_kernel(int E) {
    int e = blockIdx.x * blockDim.x + threadIdx.x;
    if (e >= E) return;
    int pos = atomicAdd(&g_cur[g_seg[e]], 1);
    g_srcs[pos] = g_src[e];
}

// ---------------- weight packing: fp32 -> bf16 hi/lo, [l][n][k] ------------
__global__ void pack_w_kernel(const float* __restrict__ Wsk,
                              const float* __restrict__ Wfsk,
                              const float* __restrict__ Wr,
                              const float* __restrict__ Wf) {
    int idx = blockIdx.x * blockDim.x + threadIdx.x;
    const int total = LAY * DC * DH;
    if (idx >= total) return;
    int k = idx % DH;
    int n = (idx / DH) % DC;
    int l = idx / (DH * DC);
    float v;
    if (n < 128) {
        v = Wsk[((size_t)l * DH + k) * DH + n];
    } else if (n < 384) {
        v = Wfsk[((size_t)l * DH + k) * 256 + (n - 128)];
    } else if (n < 896) {
        int cc = n - 384; int r = cc >> 7; int c = cc & 127;
        v = Wr[(((size_t)l * RRL + r) * DH + k) * DH + c];
    } else {
        int cc = n - 896; int r = cc >> 8; int c = cc & 255;
        v = Wf[(((size_t)l * RRL + r) * DH + k) * 256 + c];
    }
    __nv_bfloat16 h = __float2bfloat16(v);
    g_Whi[idx] = h;
    g_Wlo[idx] = __float2bfloat16(v - __bfloat162float(h));
}

// ---------------- A conversion: fp32 (+BN) -> bf16 hi/lo --------------------
__global__ void convert_a_kernel(const float* __restrict__ Aex,
                                 int use_internal, int use_bn, int M) {
    int idx = blockIdx.x * blockDim.x + threadIdx.x;
    if (idx >= M * DH) return;
    int c = idx & 127;
    const float* A = use_internal ? g_hacc : Aex;
    float v = A[idx];
    if (use_bn) v = fmaf(v, g_scale[c], g_shift[c]);
    __nv_bfloat16 h = __float2bfloat16(v);
    g_Ahi[idx] = h;
    g_Alo[idx] = __float2bfloat16(v - __bfloat162float(h));
}

// ---------------- HMMA GEMM: C[M,1920] = A[M,128] @ W^T ---------------------
// 128x128 tile per block, full K=128 in SMEM, 8 warps each m64n32,
// bf16-split x3 passes into fp32 accumulators via mma.m16n8k16.
__global__ __launch_bounds__(256, 1) void gemm_hmma_kernel(int layer, int M) {
    extern __shared__ __nv_bfloat16 sm[];
    __nv_bfloat16* sAh = sm;
    __nv_bfloat16* sAl = sm + 128 * ASTR;
    __nv_bfloat16* sBh = sm + 2 * 128 * ASTR;
    __nv_bfloat16* sBl = sm + 3 * 128 * ASTR;

    int tid = threadIdx.x, lane = tid & 31, w = tid >> 5;
    int bn = blockIdx.x * 128, bm = blockIdx.y * 128;

    // ---- load tiles (row = tid/2, half-row = tid&1)
    {
        int r = tid >> 1, h = tid & 1;
        int gr = bm + r;
        uint4 z = make_uint4(0u, 0u, 0u, 0u);
        const uint4* ah = (const uint4*)(g_Ahi + (size_t)gr * DH + h * 64);
        const uint4* al = (const uint4*)(g_Alo + (size_t)gr * DH + h * 64);
        size_t nb = (size_t)layer * DC + bn + r;
        const uint4* bh = (const uint4*)(g_Whi + nb * DH + h * 64);
        const uint4* bl = (const uint4*)(g_Wlo + nb * DH + h * 64);
#pragma unroll
        for (int j = 0; j < 8; j++) {
            *(uint4*)(sAh + r * ASTR + h * 64 + j * 8) = (gr < M) ? ah[j] : z;
            *(uint4*)(sAl + r * ASTR + h * 64 + j * 8) = (gr < M) ? al[j] : z;
            *(uint4*)(sBh + r * ASTR + h * 64 + j * 8) = bh[j];
            *(uint4*)(sBl + r * ASTR + h * 64 + j * 8) = bl[j];
        }
    }
    __syncthreads();

    int wm = w >> 2;       // 0..1 -> 64 rows
    int wn = w & 3;        // 0..3 -> 32 cols
    float acc[4][4][4];
#pragma unroll
    for (int i = 0; i < 4; i++)
#pragma unroll
        for (int j = 0; j < 4; j++)
#pragma unroll
            for (int q = 0; q < 4; q++) acc[i][j][q] = 0.0f;

    int a_r = (lane & 15), a_c = (lane >> 4) * 8;
    int b_r = ((lane >> 4) << 3) + (lane & 7), b_c = ((lane >> 3) & 1) * 8;

#pragma unroll
    for (int pass = 0; pass < 3; pass++) {
        const __nv_bfloat16* pA = (pass == 2) ? sAl : sAh;
        const __nv_bfloat16* pB = (pass == 1) ? sBl : sBh;
        uint32_t baseA = smem_u32(pA);
        uint32_t baseB = smem_u32(pB);
#pragma unroll
        for (int ks = 0; ks < 8; ks++) {
            int k0 = ks * 16;
            uint32_t af[4][4];
            uint32_t bf[4][2];
#pragma unroll
            for (int mt = 0; mt < 4; mt++) {
                uint32_t addr = baseA +
                    (uint32_t)(((wm * 64 + mt * 16 + a_r) * ASTR + k0 + a_c) * 2);
                asm volatile("ldmatrix.sync.aligned.m8n8.x4.shared.b16 {%0,%1,%2,%3}, [%4];"
                             : "=r"(af[mt][0]), "=r"(af[mt][1]), "=r"(af[mt][2]), "=r"(af[mt][3])
                             : "r"(addr));
            }
#pragma unroll
            for (int np = 0; np < 2; np++) {
                uint32_t addr = baseB +
                    (uint32_t)(((wn * 32 + np * 16 + b_r) * ASTR + k0 + b_c) * 2);
                uint32_t r0, r1, r2, r3;
                asm volatile("ldmatrix.sync.aligned.m8n8.x4.shared.b16 {%0,%1,%2,%3}, [%4];"
                             : "=r"(r0), "=r"(r1), "=r"(r2), "=r"(r3)
                             : "r"(addr));
                bf[np * 2][0] = r0;     bf[np * 2][1] = r1;
                bf[np * 2 + 1][0] = r2; bf[np * 2 + 1][1] = r3;
            }
#pragma unroll
            for (int mt = 0; mt < 4; mt++)
#pragma unroll
                for (int nt = 0; nt < 4; nt++) {
                    asm volatile(
                        "mma.sync.aligned.m16n8k16.row.col.f32.bf16.bf16.f32 "
                        "{%0,%1,%2,%3}, {%4,%5,%6,%7}, {%8,%9}, {%0,%1,%2,%3};"
                        : "+f"(acc[mt][nt][0]), "+f"(acc[mt][nt][1]),
                          "+f"(acc[mt][nt][2]), "+f"(acc[mt][nt][3])
                        : "r"(af[mt][0]), "r"(af[mt][1]), "r"(af[mt][2]), "r"(af[mt][3]),
                          "r"(bf[nt][0]), "r"(bf[nt][1]));
                }
        }
    }

    // ---- epilogue: fp32 stores straight to g_C
    int row0 = bm + wm * 64 + (lane >> 2);
    int col0 = bn + wn * 32 + (lane & 3) * 2;
#pragma unroll
    for (int mt = 0; mt < 4; mt++) {
#pragma unroll
        for (int nt = 0; nt < 4; nt++) {
            int r = row0 + mt * 16;
            int cc = col0 + nt * 8;
            if (r < M)
                *(float2*)(g_C + (size_t)r * DC + cc) =
                    make_float2(acc[mt][nt][0], acc[mt][nt][1]);
            if (r + 8 < M)
                *(float2*)(g_C + (size_t)(r + 8) * DC + cc) =
                    make_float2(acc[mt][nt][2], acc[mt][nt][3]);
        }
    }
}

// ---------------- self path -------------------------------------------------
__global__ void self_film_kernel(int M) {
    int idx = blockIdx.x * blockDim.x + threadIdx.x;
    if (idx >= M * DH) return;
    int n = idx >> 7;
    int c = idx & 127;
    const float* row = g_C + (size_t)n * DC;
    float skip  = row[c];
    float beta  = row[128 + c];
    float gamma = row[256 + c];
    float v = fmaf(gamma, skip, beta);
    g_hacc[idx] = v > 0.f ? v : 0.f;
}

// ---------------- segment-sorted edge aggregation ---------------------------
__global__ void seg_msg_kernel() {
    int gt = blockIdx.x * blockDim.x + threadIdx.x;
    int seg = gt >> 5;
    int lane = gt & 31;
    if (seg >= NSEG) return;
    int cnt = g_cnt[seg];
    if (cnt == 0) return;
    int n = seg >> 2;
    int r = seg & 3;
    int c0 = lane * 4;

    const float* dbase = g_C + (size_t)n * DC + 896 + r * 256 + c0;
    float4 be = *(const float4*)(dbase);
    float4 ga = *(const float4*)(dbase + 128);
    float4 acc = make_float4(0.f, 0.f, 0.f, 0.f);
    int base = g_off[seg];
    const float* sb = g_C + 384 + r * 128 + c0;

    for (int i0 = 0; i0 < cnt; i0 += 32) {
        int m = cnt - i0; if (m > 32) m = 32;
        int sv = (lane < m) ? g_srcs[base + i0 + lane] : 0;
        for (int i = 0; i < m; i++) {
            int s = __shfl_sync(0xffffffffu, sv, i);
            float4 xr = *(const float4*)(sb + (size_t)s * DC);
            acc.x += fmaxf(fmaf(ga.x, xr.x, be.x), 0.f);
            acc.y += fmaxf(fmaf(ga.y, xr.y, be.y), 0.f);
            acc.z += fmaxf(fmaf(ga.z, xr.z, be.z), 0.f);
            acc.w += fmaxf(fmaf(ga.w, xr.w, be.w), 0.f);
        }
    }
    float inv = 1.0f / (float)cnt;
    float* h = g_hacc + (size_t)n * DH + c0;
    atomicAdd(h + 0, acc.x * inv);
    atomicAdd(h + 1, acc.y * inv);
    atomicAdd(h + 2, acc.z * inv);
    atomicAdd(h + 3, acc.w * inv);
}

// ---------------- batchnorm stats -------------------------------------------
__global__ void zero_stats_kernel() {
    int c = threadIdx.x;
    g_sum[c] = 0.0; g_sumsq[c] = 0.0;
}

__global__ void bn_stats_kernel(int M) {
    int c = threadIdx.x;
    float s = 0.f, s2 = 0.f;
    for (int r = blockIdx.x; r < M; r += gridDim.x) {
        float v = g_hacc[(size_t)r * DH + c];
        s += v;
        s2 += v * v;
    }
    atomicAdd(&g_sum[c], (double)s);
    atomicAdd(&g_sumsq[c], (double)s2);
}

__global__ void bn_final_kernel(const float* __restrict__ bnw,
                                const float* __restrict__ bnb, int M) {
    int c = threadIdx.x;
    double mu  = g_sum[c] / (double)M;
    double var = g_sumsq[c] / (double)M - mu * mu;
    float sc = bnw[c] * rsqrtf((float)var + 1e-5f);
    g_scale[c] = sc;
    g_shift[c] = bnb[c] - (float)mu * sc;
}

// ---------------- MLP head (applies last BN inline) ------------------------
__global__ __launch_bounds__(128) void mlp_kernel(const float* __restrict__ w1,
                                                  const float* __restrict__ b1,
                                                  const float* __restrict__ w2,
                                                  const float* __restrict__ b2,
                                                  float* __restrict__ out, int M) {
    __shared__ float s_w1[DH * DMID];
    __shared__ float s_w2[DMID * DOUT];
    __shared__ float s_b1[DMID];
    __shared__ float s_b2[DOUT];
    __shared__ float s_sc[DH], s_sh[DH];
    int tid = threadIdx.x;
    for (int i = tid; i < DH * DMID; i += blockDim.x) s_w1[i] = w1[i];
    for (int i = tid; i < DMID * DOUT; i += blockDim.x) s_w2[i] = w2[i];
    if (tid < DMID) s_b1[tid] = b1[tid];
    if (tid < DOUT) s_b2[tid] = b2[tid];
    if (tid < DH) { s_sc[tid] = g_scale[tid]; s_sh[tid] = g_shift[tid]; }
    __syncthreads();

    int n = blockIdx.x * blockDim.x + tid;
    if (n >= M) return;

    float mid[DMID];
#pragma unroll
    for (int j = 0; j < DMID; j++) mid[j] = s_b1[j];

    const float* hrow = g_hacc + (size_t)n * DH;
    for (int c = 0; c < DH; c++) {
        float hv = fmaf(hrow[c], s_sc[c], s_sh[c]);
#pragma unroll
        for (int j = 0; j < DMID; j++) mid[j] = fmaf(hv, s_w1[c * DMID + j], mid[j]);
    }
#pragma unroll
    for (int j = 0; j < DMID; j++) {
        float v = mid[j];
        mid[j] = v > 0.f ? v : 0.2f * v;
    }
    float* orow = out + (size_t)n * DOUT;
#pragma unroll
    for (int o = 0; o < DOUT; o++) {
        float acc = s_b2[o];
#pragma unroll
        for (int j = 0; j < DMID; j++) acc = fmaf(mid[j], s_w2[j * DOUT + o], acc);
        orow[o] = acc;
    }
}

// ---------------- launch ----------------------------------------------------
extern "C" void kernel_launch(void* const* d_in, const int* in_sizes, int n_in,
                              void* d_out, int out_size) {
    const float* x    = (const float*)d_in[0];
    const int*   ei32 = (const int*)d_in[1];
    const int*   et32 = (const int*)d_in[2];
    const float* Wsk  = (const float*)d_in[3];
    const float* Wfsk = (const float*)d_in[4];
    const float* Wr   = (const float*)d_in[5];
    const float* Wf   = (const float*)d_in[6];
    const float* bnw  = (const float*)d_in[7];
    const float* bnb  = (const float*)d_in[8];
    const float* l1w  = (const float*)d_in[9];
    const float* l1b  = (const float*)d_in[10];
    const float* l2w  = (const float*)d_in[11];
    const float* l2b  = (const float*)d_in[12];
    float* out = (float*)d_out;

    const int E = in_sizes[2];        // 800000
    const int M = in_sizes[0] / DH;   // 50000

    cudaFuncSetAttribute(gemm_hmma_kernel,
                         cudaFuncAttributeMaxDynamicSharedMemorySize, GEMM_SMEM);

    // ---- setup: edge sort by (dst, rel) + bf16 weight split packing
    detect_kernel<<<1, 256>>>(ei32);
    zero_cnt_kernel<<<(NSEG + 255) / 256, 256>>>();
    prep_edges_kernel<<<(E + 255) / 256, 256>>>(ei32, et32, E);
    scan1_kernel<<<SCAN_B, 1024>>>();
    scan2_kernel<<<1, 256>>>();
    scan3_kernel<<<(NSEG + 255) / 256, 256>>>();
    scatter_kernel<<<(E + 255) / 256, 256>>>(E);
    pack_w_kernel<<<(LAY * DC * DH + 255) / 256, 256>>>(Wsk, Wfsk, Wr, Wf);

    dim3 gemm_grid(DC / 128, (NN + 127) / 128);
    for (int l = 0; l < LAY; l++) {
        convert_a_kernel<<<(M * DH + 255) / 256, 256>>>(x, l == 0 ? 0 : 1, l == 0 ? 0 : 1, M);
        gemm_hmma_kernel<<<gemm_grid, 256, GEMM_SMEM>>>(l, M);
        self_film_kernel<<<(M * DH + 255) / 256, 256>>>(M);
        seg_msg_kernel<<<(NSEG * 32 + 255) / 256, 256>>>();
        zero_stats_kernel<<<1, 128>>>();
        bn_stats_kernel<<<296, 128>>>(M);
        bn_final_kernel<<<1, 128>>>(bnw + l * DH, bnb + l * DH, M);
    }
    mlp_kernel<<<(M + 127) / 128, 128>>>(l1w, l1b, l2w, l2b, out, M);
}

// round 6
// speedup vs baseline: 1.6135x; 1.0860x over previous
#include <cuda_runtime.h>
#include <cuda_bf16.h>
#include <cstdint>

// Problem constants (fixed by the reference).
#define NN   50000
#define EE   800000
#define RRL  4
#define DH   128
#define DC   1920
#define LAY  3
#define DMID 32
#define DOUT 40
#define NSEG (NN * RRL)
#define SCAN_B 196
#define ASTR 136                              // padded SMEM row stride (bf16 elems)
#define GEMM_SMEM (4 * 128 * ASTR * 2)        // A hi/lo + B hi/lo = 139264 B

// ---------------- scratch (device globals) ---------------------------------
__device__ float  g_C[(size_t)NN * DC];
__device__ float  g_hacc[(size_t)NN * DH];
__device__ __nv_bfloat16 g_Ahi[(size_t)NN * DH];
__device__ __nv_bfloat16 g_Alo[(size_t)NN * DH];
__device__ __nv_bfloat16 g_Whi[(size_t)LAY * DC * DH];
__device__ __nv_bfloat16 g_Wlo[(size_t)LAY * DC * DH];
__device__ int    g_cnt[NSEG];
__device__ int    g_off[NSEG];
__device__ int    g_cur[NSEG];
__device__ int    g_src[EE];
__device__ int    g_seg[EE];
__device__ int    g_srcs[EE];
__device__ int    g_bsum[SCAN_B];
__device__ int    g_bsum_ex[SCAN_B];
__device__ double g_sum[DH];
__device__ double g_sumsq[DH];
__device__ float  g_scale[DH];
__device__ float  g_shift[DH];
__device__ int    g_is64;

// ---------------- helpers ----------------------------------------------------
__device__ __forceinline__ uint32_t smem_u32(const void* p) {
    uint32_t a;
    asm("{ .reg .u64 t; cvta.to.shared.u64 t, %1; cvt.u32.u64 %0, t; }" : "=r"(a) : "l"(p));
    return a;
}

// ---------------- dtype detection ------------------------------------------
__global__ void detect_kernel(const int* __restrict__ ei32) {
    __shared__ int nz;
    if (threadIdx.x == 0) nz = 0;
    __syncthreads();
    for (int i = threadIdx.x; i < 4096; i += blockDim.x)
        if (ei32[2 * i + 1] != 0) nz = 1;
    __syncthreads();
    if (threadIdx.x == 0) g_is64 = (nz == 0) ? 1 : 0;
}

// ---------------- edge prep -------------------------------------------------
__global__ void zero_cnt_kernel() {
    int i = blockIdx.x * blockDim.x + threadIdx.x;
    if (i < NSEG) g_cnt[i] = 0;
}

__global__ void prep_edges_kernel(const int* __restrict__ ei32,
                                  const int* __restrict__ et32, int E) {
    int e = blockIdx.x * blockDim.x + threadIdx.x;
    if (e >= E) return;
    int s, d, t;
    if (g_is64) { s = ei32[2 * e]; d = ei32[2 * (E + e)]; t = et32[2 * e]; }
    else        { s = ei32[e];     d = ei32[E + e];       t = et32[e];     }
    g_src[e] = s;
    int seg = d * RRL + t;
    g_seg[e] = seg;
    atomicAdd(&g_cnt[seg], 1);
}

__global__ void scan1_kernel() {
    __shared__ int sh[1024];
    int tid = threadIdx.x;
    int g = blockIdx.x * 1024 + tid;
    int v = (g < NSEG) ? g_cnt[g] : 0;
    sh[tid] = v;
    __syncthreads();
    for (int o = 1; o < 1024; o <<= 1) {
        int t = 0;
        if (tid >= o) t = sh[tid - o];
        __syncthreads();
        sh[tid] += t;
        __syncthreads();
    }
    if (g < NSEG) g_off[g] = sh[tid] - v;
    if (tid == 1023) g_bsum[blockIdx.x] = sh[1023];
}

__global__ void scan2_kernel() {
    __shared__ int sh[256];
    int tid = threadIdx.x;
    int v = (tid < SCAN_B) ? g_bsum[tid] : 0;
    sh[tid] = v;
    __syncthreads();
    for (int o = 1; o < 256; o <<= 1) {
        int t = 0;
        if (tid >= o) t = sh[tid - o];
        __syncthreads();
        sh[tid] += t;
        __syncthreads();
    }
    if (tid < SCAN_B) g_bsum_ex[tid] = sh[tid] - v;
}

__global__ void scan3_kernel() {
    int g = blockIdx.x * blockDim.x + threadIdx.x;
    if (g >= NSEG) return;
    int o = g_off[g] + g_bsum_ex[g >> 10];
    g_off[g] = o;
    g_cur[g] = o;
}

__global__ void scatter_kernel(int E) {
    int e = blockIdx.x * blockDim.x + threadIdx.x;
    if (e >= E) return;
    int pos = atomicAdd(&g_cur[g_seg[e]], 1);
    g_srcs[pos] = g_src[e];
}

// ---------------- weight packing: fp32 -> bf16 hi/lo, [l][n][k] ------------
__global__ void pack_w_kernel(const float* __restrict__ Wsk,
                              const float* __restrict__ Wfsk,
                              const float* __restrict__ Wr,
                              const float* __restrict__ Wf) {
    int idx = blockIdx.x * blockDim.x + threadIdx.x;
    const int total = LAY * DC * DH;
    if (idx >= total) return;
    int k = idx % DH;
    int n = (idx / DH) % DC;
    int l = idx / (DH * DC);
    float v;
    if (n < 128) {
        v = Wsk[((size_t)l * DH + k) * DH + n];
    } else if (n < 384) {
        v = Wfsk[((size_t)l * DH + k) * 256 + (n - 128)];
    } else if (n < 896) {
        int cc = n - 384; int r = cc >> 7; int c = cc & 127;
        v = Wr[(((size_t)l * RRL + r) * DH + k) * DH + c];
    } else {
        int cc = n - 896; int r = cc >> 8; int c = cc & 255;
        v = Wf[(((size_t)l * RRL + r) * DH + k) * 256 + c];
    }
    __nv_bfloat16 h = __float2bfloat16(v);
    g_Whi[idx] = h;
    g_Wlo[idx] = __float2bfloat16(v - __bfloat162float(h));
}

// ---------------- A conversion: fp32 (+BN) -> bf16 hi/lo --------------------
__global__ void convert_a_kernel(const float* __restrict__ Aex,
                                 int use_internal, int use_bn, int M) {
    int idx = blockIdx.x * blockDim.x + threadIdx.x;
    if (idx >= M * DH) return;
    int c = idx & 127;
    const float* A = use_internal ? g_hacc : Aex;
    float v = A[idx];
    if (use_bn) v = fmaf(v, g_scale[c], g_shift[c]);
    __nv_bfloat16 h = __float2bfloat16(v);
    g_Ahi[idx] = h;
    g_Alo[idx] = __float2bfloat16(v - __bfloat162float(h));
}

// ---------------- HMMA GEMM: C[M,1920] = A[M,128] @ W^T ---------------------
// 128x128 tile per block, full K=128 in SMEM, 8 warps each m64n32,
// bf16-split x3 passes into fp32 accumulators via mma.m16n8k16.
__global__ __launch_bounds__(256, 1) void gemm_hmma_kernel(int layer, int M) {
    extern __shared__ __nv_bfloat16 sm[];
    __nv_bfloat16* sAh = sm;
    __nv_bfloat16* sAl = sm + 128 * ASTR;
    __nv_bfloat16* sBh = sm + 2 * 128 * ASTR;
    __nv_bfloat16* sBl = sm + 3 * 128 * ASTR;

    int tid = threadIdx.x, lane = tid & 31, w = tid >> 5;
    int bn = blockIdx.x * 128, bm = blockIdx.y * 128;

    // ---- load tiles (row = tid/2, half-row = tid&1)
    {
        int r = tid >> 1, h = tid & 1;
        int gr = bm + r;
        uint4 z = make_uint4(0u, 0u, 0u, 0u);
        const uint4* ah = (const uint4*)(g_Ahi + (size_t)gr * DH + h * 64);
        const uint4* al = (const uint4*)(g_Alo + (size_t)gr * DH + h * 64);
        size_t nb = (size_t)layer * DC + bn + r;
        const uint4* bh = (const uint4*)(g_Whi + nb * DH + h * 64);
        const uint4* bl = (const uint4*)(g_Wlo + nb * DH + h * 64);
#pragma unroll
        for (int j = 0; j < 8; j++) {
            *(uint4*)(sAh + r * ASTR + h * 64 + j * 8) = (gr < M) ? ah[j] : z;
            *(uint4*)(sAl + r * ASTR + h * 64 + j * 8) = (gr < M) ? al[j] : z;
            *(uint4*)(sBh + r * ASTR + h * 64 + j * 8) = bh[j];
            *(uint4*)(sBl + r * ASTR + h * 64 + j * 8) = bl[j];
        }
    }
    __syncthreads();

    int wm = w >> 2;       // 0..1 -> 64 rows
    int wn = w & 3;        // 0..3 -> 32 cols
    float acc[4][4][4];
#pragma unroll
    for (int i = 0; i < 4; i++)
#pragma unroll
        for (int j = 0; j < 4; j++)
#pragma unroll
            for (int q = 0; q < 4; q++) acc[i][j][q] = 0.0f;

    int a_r = (lane & 15), a_c = (lane >> 4) * 8;
    int b_r = ((lane >> 4) << 3) + (lane & 7), b_c = ((lane >> 3) & 1) * 8;

#pragma unroll
    for (int pass = 0; pass < 3; pass++) {
        const __nv_bfloat16* pA = (pass == 2) ? sAl : sAh;
        const __nv_bfloat16* pB = (pass == 1) ? sBl : sBh;
        uint32_t baseA = smem_u32(pA);
        uint32_t baseB = smem_u32(pB);
#pragma unroll
        for (int ks = 0; ks < 8; ks++) {
            int k0 = ks * 16;
            uint32_t af[4][4];
            uint32_t bf[4][2];
#pragma unroll
            for (int mt = 0; mt < 4; mt++) {
                uint32_t addr = baseA +
                    (uint32_t)(((wm * 64 + mt * 16 + a_r) * ASTR + k0 + a_c) * 2);
                asm volatile("ldmatrix.sync.aligned.m8n8.x4.shared.b16 {%0,%1,%2,%3}, [%4];"
                             : "=r"(af[mt][0]), "=r"(af[mt][1]), "=r"(af[mt][2]), "=r"(af[mt][3])
                             : "r"(addr));
            }
#pragma unroll
            for (int np = 0; np < 2; np++) {
                uint32_t addr = baseB +
                    (uint32_t)(((wn * 32 + np * 16 + b_r) * ASTR + k0 + b_c) * 2);
                uint32_t r0, r1, r2, r3;
                asm volatile("ldmatrix.sync.aligned.m8n8.x4.shared.b16 {%0,%1,%2,%3}, [%4];"
                             : "=r"(r0), "=r"(r1), "=r"(r2), "=r"(r3)
                             : "r"(addr));
                bf[np * 2][0] = r0;     bf[np * 2][1] = r1;
                bf[np * 2 + 1][0] = r2; bf[np * 2 + 1][1] = r3;
            }
#pragma unroll
            for (int mt = 0; mt < 4; mt++)
#pragma unroll
                for (int nt = 0; nt < 4; nt++) {
                    asm volatile(
                        "mma.sync.aligned.m16n8k16.row.col.f32.bf16.bf16.f32 "
                        "{%0,%1,%2,%3}, {%4,%5,%6,%7}, {%8,%9}, {%0,%1,%2,%3};"
                        : "+f"(acc[mt][nt][0]), "+f"(acc[mt][nt][1]),
                          "+f"(acc[mt][nt][2]), "+f"(acc[mt][nt][3])
                        : "r"(af[mt][0]), "r"(af[mt][1]), "r"(af[mt][2]), "r"(af[mt][3]),
                          "r"(bf[nt][0]), "r"(bf[nt][1]));
                }
        }
    }

    // ---- epilogue: fp32 stores straight to g_C
    int row0 = bm + wm * 64 + (lane >> 2);
    int col0 = bn + wn * 32 + (lane & 3) * 2;
#pragma unroll
    for (int mt = 0; mt < 4; mt++) {
#pragma unroll
        for (int nt = 0; nt < 4; nt++) {
            int r = row0 + mt * 16;
            int cc = col0 + nt * 8;
            if (r < M)
                *(float2*)(g_C + (size_t)r * DC + cc) =
                    make_float2(acc[mt][nt][0], acc[mt][nt][1]);
            if (r + 8 < M)
                *(float2*)(g_C + (size_t)(r + 8) * DC + cc) =
                    make_float2(acc[mt][nt][2], acc[mt][nt][3]);
        }
    }
}

// ---------------- fused self path + segment aggregation ---------------------
// One warp per node: computes relu(gamma_s*skip+beta_s) + sum_r mean_msg(r),
// plain stores (no atomics).
__global__ void node_agg_kernel(int M) {
    int gt = blockIdx.x * blockDim.x + threadIdx.x;
    int n = gt >> 5;
    int lane = gt & 31;
    if (n >= M) return;
    int c0 = lane * 4;
    const float* row = g_C + (size_t)n * DC;

    float4 skip = *(const float4*)(row + c0);
    float4 bs   = *(const float4*)(row + 128 + c0);
    float4 gs   = *(const float4*)(row + 256 + c0);
    float4 h;
    h.x = fmaxf(fmaf(gs.x, skip.x, bs.x), 0.f);
    h.y = fmaxf(fmaf(gs.y, skip.y, bs.y), 0.f);
    h.z = fmaxf(fmaf(gs.z, skip.z, bs.z), 0.f);
    h.w = fmaxf(fmaf(gs.w, skip.w, bs.w), 0.f);

#pragma unroll
    for (int r = 0; r < RRL; r++) {
        int seg = n * RRL + r;
        int cnt = g_cnt[seg];
        if (cnt == 0) continue;
        float4 be = *(const float4*)(row + 896 + r * 256 + c0);
        float4 ga = *(const float4*)(row + 896 + r * 256 + 128 + c0);
        float4 acc = make_float4(0.f, 0.f, 0.f, 0.f);
        int base = g_off[seg];
        const float* sb = g_C + 384 + r * 128 + c0;
        for (int i = 0; i < cnt; i++) {
            int s = __ldg(&g_srcs[base + i]);
            float4 xr = *(const float4*)(sb + (size_t)s * DC);
            acc.x += fmaxf(fmaf(ga.x, xr.x, be.x), 0.f);
            acc.y += fmaxf(fmaf(ga.y, xr.y, be.y), 0.f);
            acc.z += fmaxf(fmaf(ga.z, xr.z, be.z), 0.f);
            acc.w += fmaxf(fmaf(ga.w, xr.w, be.w), 0.f);
        }
        float inv = 1.0f / (float)cnt;
        h.x = fmaf(acc.x, inv, h.x);
        h.y = fmaf(acc.y, inv, h.y);
        h.z = fmaf(acc.z, inv, h.z);
        h.w = fmaf(acc.w, inv, h.w);
    }
    *(float4*)(g_hacc + (size_t)n * DH + c0) = h;
}

// ---------------- batchnorm stats -------------------------------------------
__global__ void zero_stats_kernel() {
    int c = threadIdx.x;
    g_sum[c] = 0.0; g_sumsq[c] = 0.0;
}

__global__ void bn_stats_kernel(int M) {
    int c = threadIdx.x;
    float s = 0.f, s2 = 0.f;
    for (int r = blockIdx.x; r < M; r += gridDim.x) {
        float v = g_hacc[(size_t)r * DH + c];
        s += v;
        s2 += v * v;
    }
    atomicAdd(&g_sum[c], (double)s);
    atomicAdd(&g_sumsq[c], (double)s2);
}

__global__ void bn_final_kernel(const float* __restrict__ bnw,
                                const float* __restrict__ bnb, int M) {
    int c = threadIdx.x;
    double mu  = g_sum[c] / (double)M;
    double var = g_sumsq[c] / (double)M - mu * mu;
    float sc = bnw[c] * rsqrtf((float)var + 1e-5f);
    g_scale[c] = sc;
    g_shift[c] = bnb[c] - (float)mu * sc;
}

// ---------------- MLP head (applies last BN inline) ------------------------
__global__ __launch_bounds__(128) void mlp_kernel(const float* __restrict__ w1,
                                                  const float* __restrict__ b1,
                                                  const float* __restrict__ w2,
                                                  const float* __restrict__ b2,
                                                  float* __restrict__ out, int M) {
    __shared__ float s_w1[DH * DMID];
    __shared__ float s_w2[DMID * DOUT];
    __shared__ float s_b1[DMID];
    __shared__ float s_b2[DOUT];
    __shared__ float s_sc[DH], s_sh[DH];
    int tid = threadIdx.x;
    for (int i = tid; i < DH * DMID; i += blockDim.x) s_w1[i] = w1[i];
    for (int i = tid; i < DMID * DOUT; i += blockDim.x) s_w2[i] = w2[i];
    if (tid < DMID) s_b1[tid] = b1[tid];
    if (tid < DOUT) s_b2[tid] = b2[tid];
    if (tid < DH) { s_sc[tid] = g_scale[tid]; s_sh[tid] = g_shift[tid]; }
    __syncthreads();

    int n = blockIdx.x * blockDim.x + tid;
    if (n >= M) return;

    float mid[DMID];
#pragma unroll
    for (int j = 0; j < DMID; j++) mid[j] = s_b1[j];

    const float* hrow = g_hacc + (size_t)n * DH;
    for (int c = 0; c < DH; c++) {
        float hv = fmaf(hrow[c], s_sc[c], s_sh[c]);
#pragma unroll
        for (int j = 0; j < DMID; j++) mid[j] = fmaf(hv, s_w1[c * DMID + j], mid[j]);
    }
#pragma unroll
    for (int j = 0; j < DMID; j++) {
        float v = mid[j];
        mid[j] = v > 0.f ? v : 0.2f * v;
    }
    float* orow = out + (size_t)n * DOUT;
#pragma unroll
    for (int o = 0; o < DOUT; o++) {
        float acc = s_b2[o];
#pragma unroll
        for (int j = 0; j < DMID; j++) acc = fmaf(mid[j], s_w2[j * DOUT + o], acc);
        orow[o] = acc;
    }
}

// ---------------- launch ----------------------------------------------------
extern "C" void kernel_launch(void* const* d_in, const int* in_sizes, int n_in,
                              void* d_out, int out_size) {
    const float* x    = (const float*)d_in[0];
    const int*   ei32 = (const int*)d_in[1];
    const int*   et32 = (const int*)d_in[2];
    const float* Wsk  = (const float*)d_in[3];
    const float* Wfsk = (const float*)d_in[4];
    const float* Wr   = (const float*)d_in[5];
    const float* Wf   = (const float*)d_in[6];
    const float* bnw  = (const float*)d_in[7];
    const float* bnb  = (const float*)d_in[8];
    const float* l1w  = (const float*)d_in[9];
    const float* l1b  = (const float*)d_in[10];
    const float* l2w  = (const float*)d_in[11];
    const float* l2b  = (const float*)d_in[12];
    float* out = (float*)d_out;

    const int E = in_sizes[2];        // 800000
    const int M = in_sizes[0] / DH;   // 50000

    cudaFuncSetAttribute(gemm_hmma_kernel,
                         cudaFuncAttributeMaxDynamicSharedMemorySize, GEMM_SMEM);

    dim3 gemm_grid(DC / 128, (NN + 127) / 128);

    // Launch order puts gemm_hmma in ncu's captured slot (4th launch).
    pack_w_kernel<<<(LAY * DC * DH + 255) / 256, 256>>>(Wsk, Wfsk, Wr, Wf);      // 1
    convert_a_kernel<<<(M * DH + 255) / 256, 256>>>(x, 0, 0, M);                 // 2
    detect_kernel<<<1, 256>>>(ei32);                                             // 3
    gemm_hmma_kernel<<<gemm_grid, 256, GEMM_SMEM>>>(0, M);                       // 4 (profiled)

    // Edge prep (independent of layer-0 GEMM).
    zero_cnt_kernel<<<(NSEG + 255) / 256, 256>>>();
    prep_edges_kernel<<<(E + 255) / 256, 256>>>(ei32, et32, E);
    scan1_kernel<<<SCAN_B, 1024>>>();
    scan2_kernel<<<1, 256>>>();
    scan3_kernel<<<(NSEG + 255) / 256, 256>>>();
    scatter_kernel<<<(E + 255) / 256, 256>>>(E);

    for (int l = 0; l < LAY; l++) {
        if (l > 0) {
            convert_a_kernel<<<(M * DH + 255) / 256, 256>>>(x, 1, 1, M);
            gemm_hmma_kernel<<<gemm_grid, 256, GEMM_SMEM>>>(l, M);
        }
        node_agg_kernel<<<(M * 32 + 255) / 256, 256>>>(M);
        zero_stats_kernel<<<1, 128>>>();
        bn_stats_kernel<<<296, 128>>>(M);
        bn_final_kernel<<<1, 128>>>(bnw + l * DH, bnb + l * DH, M);
    }
    mlp_kernel<<<(M + 127) / 128, 128>>>(l1w, l1b, l2w, l2b, out, M);
}

// round 7
// speedup vs baseline: 1.6250x; 1.0072x over previous
#include <cuda_runtime.h>
#include <cuda_bf16.h>
#include <cstdint>

// Problem constants (fixed by the reference).
#define NN   50000
#define EE   800000
#define RRL  4
#define DH   128
#define DC   1920
#define LAY  3
#define DMID 32
#define DOUT 40
#define NSEG (NN * RRL)
#define SCAN_B 196
#define ASTR 136                              // padded SMEM row stride (bf16 elems)
#define GEMM_SMEM (4 * 128 * ASTR * 2)        // A hi/lo + B hi/lo = 139264 B

// ---------------- scratch (device globals) ---------------------------------
__device__ float  g_C[(size_t)NN * DC];
__device__ float  g_hacc[(size_t)NN * DH];
__device__ __nv_bfloat16 g_Ahi[(size_t)NN * DH];
__device__ __nv_bfloat16 g_Alo[(size_t)NN * DH];
__device__ __nv_bfloat16 g_Whi[(size_t)LAY * DC * DH];
__device__ __nv_bfloat16 g_Wlo[(size_t)LAY * DC * DH];
__device__ int    g_cnt[NSEG];
__device__ int    g_off[NSEG];
__device__ int    g_cur[NSEG];
__device__ int    g_src[EE];
__device__ int    g_seg[EE];
__device__ int    g_srcs[EE];
__device__ int    g_bsum[SCAN_B];
__device__ int    g_bsum_ex[SCAN_B];
__device__ double g_sum[DH];
__device__ double g_sumsq[DH];
__device__ float  g_scale[DH];
__device__ float  g_shift[DH];
__device__ int    g_is64;

// ---------------- helpers ----------------------------------------------------
__device__ __forceinline__ uint32_t smem_u32(const void* p) {
    uint32_t a;
    asm("{ .reg .u64 t; cvta.to.shared.u64 t, %1; cvt.u32.u64 %0, t; }" : "=r"(a) : "l"(p));
    return a;
}

// ---------------- dtype detection ------------------------------------------
__global__ void detect_kernel(const int* __restrict__ ei32) {
    __shared__ int nz;
    if (threadIdx.x == 0) nz = 0;
    __syncthreads();
    for (int i = threadIdx.x; i < 4096; i += blockDim.x)
        if (ei32[2 * i + 1] != 0) nz = 1;
    __syncthreads();
    if (threadIdx.x == 0) g_is64 = (nz == 0) ? 1 : 0;
}

// ---------------- edge prep -------------------------------------------------
__global__ void zero_cnt_kernel() {
    int i = blockIdx.x * blockDim.x + threadIdx.x;
    if (i < NSEG) g_cnt[i] = 0;
}

__global__ void prep_edges_kernel(const int* __restrict__ ei32,
                                  const int* __restrict__ et32, int E) {
    int e = blockIdx.x * blockDim.x + threadIdx.x;
    if (e >= E) return;
    int s, d, t;
    if (g_is64) { s = ei32[2 * e]; d = ei32[2 * (E + e)]; t = et32[2 * e]; }
    else        { s = ei32[e];     d = ei32[E + e];       t = et32[e];     }
    g_src[e] = s;
    int seg = d * RRL + t;
    g_seg[e] = seg;
    atomicAdd(&g_cnt[seg], 1);
}

__global__ void scan1_kernel() {
    __shared__ int sh[1024];
    int tid = threadIdx.x;
    int g = blockIdx.x * 1024 + tid;
    int v = (g < NSEG) ? g_cnt[g] : 0;
    sh[tid] = v;
    __syncthreads();
    for (int o = 1; o < 1024; o <<= 1) {
        int t = 0;
        if (tid >= o) t = sh[tid - o];
        __syncthreads();
        sh[tid] += t;
        __syncthreads();
    }
    if (g < NSEG) g_off[g] = sh[tid] - v;
    if (tid == 1023) g_bsum[blockIdx.x] = sh[1023];
}

__global__ void scan2_kernel() {
    __shared__ int sh[256];
    int tid = threadIdx.x;
    int v = (tid < SCAN_B) ? g_bsum[tid] : 0;
    sh[tid] = v;
    __syncthreads();
    for (int o = 1; o < 256; o <<= 1) {
        int t = 0;
        if (tid >= o) t = sh[tid - o];
        __syncthreads();
        sh[tid] += t;
        __syncthreads();
    }
    if (tid < SCAN_B) g_bsum_ex[tid] = sh[tid] - v;
}

__global__ void scan3_kernel() {
    int g = blockIdx.x * blockDim.x + threadIdx.x;
    if (g >= NSEG) return;
    int o = g_off[g] + g_bsum_ex[g >> 10];
    g_off[g] = o;
    g_cur[g] = o;
}

__global__ void scatter_kernel(int E) {
    int e = blockIdx.x * blockDim.x + threadIdx.x;
    if (e >= E) return;
    int pos = atomicAdd(&g_cur[g_seg[e]], 1);
    g_srcs[pos] = g_src[e];
}

// ---------------- weight packing: fp32 -> bf16 hi/lo, [l][n][k] ------------
__global__ void pack_w_kernel(const float* __restrict__ Wsk,
                              const float* __restrict__ Wfsk,
                              const float* __restrict__ Wr,
                              const float* __restrict__ Wf) {
    int idx = blockIdx.x * blockDim.x + threadIdx.x;
    const int total = LAY * DC * DH;
    if (idx >= total) return;
    int k = idx % DH;
    int n = (idx / DH) % DC;
    int l = idx / (DH * DC);
    float v;
    if (n < 128) {
        v = Wsk[((size_t)l * DH + k) * DH + n];
    } else if (n < 384) {
        v = Wfsk[((size_t)l * DH + k) * 256 + (n - 128)];
    } else if (n < 896) {
        int cc = n - 384; int r = cc >> 7; int c = cc & 127;
        v = Wr[(((size_t)l * RRL + r) * DH + k) * DH + c];
    } else {
        int cc = n - 896; int r = cc >> 8; int c = cc & 255;
        v = Wf[(((size_t)l * RRL + r) * DH + k) * 256 + c];
    }
    __nv_bfloat16 h = __float2bfloat16(v);
    g_Whi[idx] = h;
    g_Wlo[idx] = __float2bfloat16(v - __bfloat162float(h));
}

// ---------------- A conversion: fp32 (+BN) -> bf16 hi/lo --------------------
__global__ void convert_a_kernel(const float* __restrict__ Aex,
                                 int use_internal, int use_bn, int M) {
    int idx = blockIdx.x * blockDim.x + threadIdx.x;
    if (idx >= M * DH) return;
    int c = idx & 127;
    const float* A = use_internal ? g_hacc : Aex;
    float v = A[idx];
    if (use_bn) v = fmaf(v, g_scale[c], g_shift[c]);
    __nv_bfloat16 h = __float2bfloat16(v);
    g_Ahi[idx] = h;
    g_Alo[idx] = __float2bfloat16(v - __bfloat162float(h));
}

// ---------------- HMMA GEMM: C[M,1920] = A[M,128] @ W^T ---------------------
// 128x128 tile per block, full K=128 in SMEM, 8 warps each m64n32.
// bf16-split: all hi/lo fragments loaded ONCE per k-step, then
// acc += Ah*Bh + Ah*Bl + Al*Bh  (fp32 accum).
__global__ __launch_bounds__(256, 1) void gemm_hmma_kernel(int layer, int M) {
    extern __shared__ __nv_bfloat16 sm[];
    __nv_bfloat16* sAh = sm;
    __nv_bfloat16* sAl = sm + 128 * ASTR;
    __nv_bfloat16* sBh = sm + 2 * 128 * ASTR;
    __nv_bfloat16* sBl = sm + 3 * 128 * ASTR;

    int tid = threadIdx.x, lane = tid & 31, w = tid >> 5;
    int bn = blockIdx.x * 128, bm = blockIdx.y * 128;

    // ---- load tiles (row = tid/2, half-row = tid&1)
    {
        int r = tid >> 1, h = tid & 1;
        int gr = bm + r;
        uint4 z = make_uint4(0u, 0u, 0u, 0u);
        const uint4* ah = (const uint4*)(g_Ahi + (size_t)gr * DH + h * 64);
        const uint4* al = (const uint4*)(g_Alo + (size_t)gr * DH + h * 64);
        size_t nb = (size_t)layer * DC + bn + r;
        const uint4* bh = (const uint4*)(g_Whi + nb * DH + h * 64);
        const uint4* bl = (const uint4*)(g_Wlo + nb * DH + h * 64);
#pragma unroll
        for (int j = 0; j < 8; j++) {
            *(uint4*)(sAh + r * ASTR + h * 64 + j * 8) = (gr < M) ? ah[j] : z;
            *(uint4*)(sAl + r * ASTR + h * 64 + j * 8) = (gr < M) ? al[j] : z;
            *(uint4*)(sBh + r * ASTR + h * 64 + j * 8) = bh[j];
            *(uint4*)(sBl + r * ASTR + h * 64 + j * 8) = bl[j];
        }
    }
    __syncthreads();

    int wm = w >> 2;       // 0..1 -> 64 rows
    int wn = w & 3;        // 0..3 -> 32 cols
    float acc[4][4][4];
#pragma unroll
    for (int i = 0; i < 4; i++)
#pragma unroll
        for (int j = 0; j < 4; j++)
#pragma unroll
            for (int q = 0; q < 4; q++) acc[i][j][q] = 0.0f;

    int a_r = (lane & 15), a_c = (lane >> 4) * 8;
    int b_r = ((lane >> 4) << 3) + (lane & 7), b_c = ((lane >> 3) & 1) * 8;

    uint32_t baseAh = smem_u32(sAh), baseAl = smem_u32(sAl);
    uint32_t baseBh = smem_u32(sBh), baseBl = smem_u32(sBl);

#pragma unroll 1
    for (int ks = 0; ks < 8; ks++) {
        int k0 = ks * 16;
        uint32_t afh[4][4], afl[4][4];
        uint32_t bfh[4][2], bfl[4][2];
        uint32_t aoff = (uint32_t)(((wm * 64 + a_r) * ASTR + k0 + a_c) * 2);
        uint32_t boff = (uint32_t)(((wn * 32 + b_r) * ASTR + k0 + b_c) * 2);
#pragma unroll
        for (int mt = 0; mt < 4; mt++) {
            uint32_t ad = aoff + (uint32_t)(mt * 16 * ASTR * 2);
            asm volatile("ldmatrix.sync.aligned.m8n8.x4.shared.b16 {%0,%1,%2,%3}, [%4];"
                         : "=r"(afh[mt][0]), "=r"(afh[mt][1]), "=r"(afh[mt][2]), "=r"(afh[mt][3])
                         : "r"(baseAh + ad));
            asm volatile("ldmatrix.sync.aligned.m8n8.x4.shared.b16 {%0,%1,%2,%3}, [%4];"
                         : "=r"(afl[mt][0]), "=r"(afl[mt][1]), "=r"(afl[mt][2]), "=r"(afl[mt][3])
                         : "r"(baseAl + ad));
        }
#pragma unroll
        for (int np = 0; np < 2; np++) {
            uint32_t bd = boff + (uint32_t)(np * 16 * ASTR * 2);
            uint32_t r0, r1, r2, r3;
            asm volatile("ldmatrix.sync.aligned.m8n8.x4.shared.b16 {%0,%1,%2,%3}, [%4];"
                         : "=r"(r0), "=r"(r1), "=r"(r2), "=r"(r3) : "r"(baseBh + bd));
            bfh[np * 2][0] = r0;     bfh[np * 2][1] = r1;
            bfh[np * 2 + 1][0] = r2; bfh[np * 2 + 1][1] = r3;
            asm volatile("ldmatrix.sync.aligned.m8n8.x4.shared.b16 {%0,%1,%2,%3}, [%4];"
                         : "=r"(r0), "=r"(r1), "=r"(r2), "=r"(r3) : "r"(baseBl + bd));
            bfl[np * 2][0] = r0;     bfl[np * 2][1] = r1;
            bfl[np * 2 + 1][0] = r2; bfl[np * 2 + 1][1] = r3;
        }
#pragma unroll
        for (int mt = 0; mt < 4; mt++)
#pragma unroll
            for (int nt = 0; nt < 4; nt++) {
                asm volatile(
                    "mma.sync.aligned.m16n8k16.row.col.f32.bf16.bf16.f32 "
                    "{%0,%1,%2,%3}, {%4,%5,%6,%7}, {%8,%9}, {%0,%1,%2,%3};"
                    : "+f"(acc[mt][nt][0]), "+f"(acc[mt][nt][1]),
                      "+f"(acc[mt][nt][2]), "+f"(acc[mt][nt][3])
                    : "r"(afh[mt][0]), "r"(afh[mt][1]), "r"(afh[mt][2]), "r"(afh[mt][3]),
                      "r"(bfh[nt][0]), "r"(bfh[nt][1]));
                asm volatile(
                    "mma.sync.aligned.m16n8k16.row.col.f32.bf16.bf16.f32 "
                    "{%0,%1,%2,%3}, {%4,%5,%6,%7}, {%8,%9}, {%0,%1,%2,%3};"
                    : "+f"(acc[mt][nt][0]), "+f"(acc[mt][nt][1]),
                      "+f"(acc[mt][nt][2]), "+f"(acc[mt][nt][3])
                    : "r"(afh[mt][0]), "r"(afh[mt][1]), "r"(afh[mt][2]), "r"(afh[mt][3]),
                      "r"(bfl[nt][0]), "r"(bfl[nt][1]));
                asm volatile(
                    "mma.sync.aligned.m16n8k16.row.col.f32.bf16.bf16.f32 "
                    "{%0,%1,%2,%3}, {%4,%5,%6,%7}, {%8,%9}, {%0,%1,%2,%3};"
                    : "+f"(acc[mt][nt][0]), "+f"(acc[mt][nt][1]),
                      "+f"(acc[mt][nt][2]), "+f"(acc[mt][nt][3])
                    : "r"(afl[mt][0]), "r"(afl[mt][1]), "r"(afl[mt][2]), "r"(afl[mt][3]),
                      "r"(bfh[nt][0]), "r"(bfh[nt][1]));
            }
    }

    // ---- epilogue: fp32 stores straight to g_C
    int row0 = bm + wm * 64 + (lane >> 2);
    int col0 = bn + wn * 32 + (lane & 3) * 2;
#pragma unroll
    for (int mt = 0; mt < 4; mt++) {
#pragma unroll
        for (int nt = 0; nt < 4; nt++) {
            int r = row0 + mt * 16;
            int cc = col0 + nt * 8;
            if (r < M)
                *(float2*)(g_C + (size_t)r * DC + cc) =
                    make_float2(acc[mt][nt][0], acc[mt][nt][1]);
            if (r + 8 < M)
                *(float2*)(g_C + (size_t)(r + 8) * DC + cc) =
                    make_float2(acc[mt][nt][2], acc[mt][nt][3]);
        }
    }
}

// ---------------- fused self path + segment aggregation ---------------------
__global__ void node_agg_kernel(int M) {
    int gt = blockIdx.x * blockDim.x + threadIdx.x;
    int n = gt >> 5;
    int lane = gt & 31;
    if (n >= M) return;
    int c0 = lane * 4;
    const float* row = g_C + (size_t)n * DC;

    float4 skip = *(const float4*)(row + c0);
    float4 bs   = *(const float4*)(row + 128 + c0);
    float4 gs   = *(const float4*)(row + 256 + c0);
    float4 h;
    h.x = fmaxf(fmaf(gs.x, skip.x, bs.x), 0.f);
    h.y = fmaxf(fmaf(gs.y, skip.y, bs.y), 0.f);
    h.z = fmaxf(fmaf(gs.z, skip.z, bs.z), 0.f);
    h.w = fmaxf(fmaf(gs.w, skip.w, bs.w), 0.f);

#pragma unroll
    for (int r = 0; r < RRL; r++) {
        int seg = n * RRL + r;
        int cnt = g_cnt[seg];
        if (cnt == 0) continue;
        float4 be = *(const float4*)(row + 896 + r * 256 + c0);
        float4 ga = *(const float4*)(row + 896 + r * 256 + 128 + c0);
        float4 acc = make_float4(0.f, 0.f, 0.f, 0.f);
        int base = g_off[seg];
        const float* sb = g_C + 384 + r * 128 + c0;
        for (int i = 0; i < cnt; i++) {
            int s = __ldg(&g_srcs[base + i]);
            float4 xr = *(const float4*)(sb + (size_t)s * DC);
            acc.x += fmaxf(fmaf(ga.x, xr.x, be.x), 0.f);
            acc.y += fmaxf(fmaf(ga.y, xr.y, be.y), 0.f);
            acc.z += fmaxf(fmaf(ga.z, xr.z, be.z), 0.f);
            acc.w += fmaxf(fmaf(ga.w, xr.w, be.w), 0.f);
        }
        float inv = 1.0f / (float)cnt;
        h.x = fmaf(acc.x, inv, h.x);
        h.y = fmaf(acc.y, inv, h.y);
        h.z = fmaf(acc.z, inv, h.z);
        h.w = fmaf(acc.w, inv, h.w);
    }
    *(float4*)(g_hacc + (size_t)n * DH + c0) = h;
}

// ---------------- batchnorm stats -------------------------------------------
__global__ void zero_stats_kernel() {
    int c = threadIdx.x;
    g_sum[c] = 0.0; g_sumsq[c] = 0.0;
}

__global__ void bn_stats_kernel(int M) {
    int c = threadIdx.x;
    float s = 0.f, s2 = 0.f;
    for (int r = blockIdx.x; r < M; r += gridDim.x) {
        float v = g_hacc[(size_t)r * DH + c];
        s += v;
        s2 += v * v;
    }
    atomicAdd(&g_sum[c], (double)s);
    atomicAdd(&g_sumsq[c], (double)s2);
}

__global__ void bn_final_kernel(const float* __restrict__ bnw,
                                const float* __restrict__ bnb, int M) {
    int c = threadIdx.x;
    double mu  = g_sum[c] / (double)M;
    double var = g_sumsq[c] / (double)M - mu * mu;
    float sc = bnw[c] * rsqrtf((float)var + 1e-5f);
    g_scale[c] = sc;
    g_shift[c] = bnb[c] - (float)mu * sc;
}

// ---------------- MLP head (applies last BN inline) ------------------------
__global__ __launch_bounds__(128) void mlp_kernel(const float* __restrict__ w1,
                                                  const float* __restrict__ b1,
                                                  const float* __restrict__ w2,
                                                  const float* __restrict__ b2,
                                                  float* __restrict__ out, int M) {
    __shared__ float s_w1[DH * DMID];
    __shared__ float s_w2[DMID * DOUT];
    __shared__ float s_b1[DMID];
    __shared__ float s_b2[DOUT];
    __shared__ float s_sc[DH], s_sh[DH];
    int tid = threadIdx.x;
    for (int i = tid; i < DH * DMID; i += blockDim.x) s_w1[i] = w1[i];
    for (int i = tid; i < DMID * DOUT; i += blockDim.x) s_w2[i] = w2[i];
    if (tid < DMID) s_b1[tid] = b1[tid];
    if (tid < DOUT) s_b2[tid] = b2[tid];
    if (tid < DH) { s_sc[tid] = g_scale[tid]; s_sh[tid] = g_shift[tid]; }
    __syncthreads();

    int n = blockIdx.x * blockDim.x + tid;
    if (n >= M) return;

    float mid[DMID];
#pragma unroll
    for (int j = 0; j < DMID; j++) mid[j] = s_b1[j];

    const float* hrow = g_hacc + (size_t)n * DH;
    for (int c = 0; c < DH; c++) {
        float hv = fmaf(hrow[c], s_sc[c], s_sh[c]);
#pragma unroll
        for (int j = 0; j < DMID; j++) mid[j] = fmaf(hv, s_w1[c * DMID + j], mid[j]);
    }
#pragma unroll
    for (int j = 0; j < DMID; j++) {
        float v = mid[j];
        mid[j] = v > 0.f ? v : 0.2f * v;
    }
    float* orow = out + (size_t)n * DOUT;
#pragma unroll
    for (int o = 0; o < DOUT; o++) {
        float acc = s_b2[o];
#pragma unroll
        for (int j = 0; j < DMID; j++) acc = fmaf(mid[j], s_w2[j * DOUT + o], acc);
        orow[o] = acc;
    }
}

// ---------------- launch ----------------------------------------------------
extern "C" void kernel_launch(void* const* d_in, const int* in_sizes, int n_in,
                              void* d_out, int out_size) {
    const float* x    = (const float*)d_in[0];
    const int*   ei32 = (const int*)d_in[1];
    const int*   et32 = (const int*)d_in[2];
    const float* Wsk  = (const float*)d_in[3];
    const float* Wfsk = (const float*)d_in[4];
    const float* Wr   = (const float*)d_in[5];
    const float* Wf   = (const float*)d_in[6];
    const float* bnw  = (const float*)d_in[7];
    const float* bnb  = (const float*)d_in[8];
    const float* l1w  = (const float*)d_in[9];
    const float* l1b  = (const float*)d_in[10];
    const float* l2w  = (const float*)d_in[11];
    const float* l2b  = (const float*)d_in[12];
    float* out = (float*)d_out;

    const int E = in_sizes[2];        // 800000
    const int M = in_sizes[0] / DH;   // 50000

    cudaFuncSetAttribute(gemm_hmma_kernel,
                         cudaFuncAttributeMaxDynamicSharedMemorySize, GEMM_SMEM);

    dim3 gemm_grid(DC / 128, (NN + 127) / 128);

    // Launch order puts gemm_hmma in ncu's captured slot (4th launch).
    pack_w_kernel<<<(LAY * DC * DH + 255) / 256, 256>>>(Wsk, Wfsk, Wr, Wf);      // 1
    convert_a_kernel<<<(M * DH + 255) / 256, 256>>>(x, 0, 0, M);                 // 2
    detect_kernel<<<1, 256>>>(ei32);                                             // 3
    gemm_hmma_kernel<<<gemm_grid, 256, GEMM_SMEM>>>(0, M);                       // 4 (profiled)

    // Edge prep (independent of layer-0 GEMM).
    zero_cnt_kernel<<<(NSEG + 255) / 256, 256>>>();
    prep_edges_kernel<<<(E + 255) / 256, 256>>>(ei32, et32, E);
    scan1_kernel<<<SCAN_B, 1024>>>();
    scan2_kernel<<<1, 256>>>();
    scan3_kernel<<<(NSEG + 255) / 256, 256>>>();
    scatter_kernel<<<(E + 255) / 256, 256>>>(E);

    for (int l = 0; l < LAY; l++) {
        if (l > 0) {
            convert_a_kernel<<<(M * DH + 255) / 256, 256>>>(x, 1, 1, M);
            gemm_hmma_kernel<<<gemm_grid, 256, GEMM_SMEM>>>(l, M);
        }
        node_agg_kernel<<<(M * 32 + 255) / 256, 256>>>(M);
        zero_stats_kernel<<<1, 128>>>();
        bn_stats_kernel<<<296, 128>>>(M);
        bn_final_kernel<<<1, 128>>>(bnw + l * DH, bnb + l * DH, M);
    }
    mlp_kernel<<<(M + 127) / 128, 128>>>(l1w, l1b, l2w, l2b, out, M);
}